// round 2
// baseline (speedup 1.0000x reference)
#include <cuda_runtime.h>
#include <cuda_bf16.h>
#include <mma.h>
#include <math.h>

using namespace nvcuda;

#define NL 4
#define DD 512
#define DII 1024
#define DSS 16
#define VV 50257
#define BB 2
#define SS 1024
#define BSS 2048   /* BB*SS */

// ---------------- scratch (static device globals; no allocations) ----------
__device__ __align__(256) float g_h[BSS * DD];          // 4 MB
__device__ __align__(256) float g_proj[BSS * 2 * DII];  // 16 MB
__device__ __align__(256) float g_xc[BSS * DII];        // 8 MB
__device__ __align__(256) float g_coeff[BSS * 48];      // 384 KB (ad|bd|c)
__device__ __align__(256) float g_yg[BSS * DII];        // 8 MB

// ---------------- helpers ---------------------------------------------------
__device__ __forceinline__ float warp_sum(float v) {
#pragma unroll
    for (int o = 16; o > 0; o >>= 1) v += __shfl_xor_sync(0xffffffffu, v, o);
    return v;
}

__device__ __forceinline__ float silu_f(float x) {
    return x * (1.0f / (1.0f + __expf(-x)));
}

// ---------------- K0: embedding gather + pos --------------------------------
__global__ void embed_kernel(const int* __restrict__ x, const float* __restrict__ emb,
                             const float* __restrict__ pos, float* __restrict__ h) {
    int bs = blockIdx.x;
    int s  = bs & (SS - 1);
    int tok = x[bs];
    const float4* e4 = (const float4*)(emb + (size_t)tok * DD);
    const float4* p4 = (const float4*)(pos + (size_t)s * DD);
    float4* h4 = (float4*)(h + (size_t)bs * DD);
    int i = threadIdx.x;           // 128 threads, 128 float4 = 512 floats
    float4 a = e4[i], p = p4[i];
    h4[i] = make_float4(a.x + p.x, a.y + p.y, a.z + p.z, a.w + p.w);
}

// ---------------- GEMM: tf32x3 (fp32-accurate) ------------------------------
// C[M,N] = A[M,K] @ B[K,N]; mode 0: plain, 1: +bias[n], 2: += addsrc[m,n]
// A,B row-major fp32. M % 128 == 0, K % 32 == 0; N arbitrary (guarded).
__global__ __launch_bounds__(256, 2)
void gemm_tf32x3(const float* __restrict__ A, const float* __restrict__ B,
                 float* __restrict__ C, int M, int N, int K,
                 const float* __restrict__ bias, const float* __restrict__ addsrc,
                 int mode) {
    __shared__ __align__(128) float sA[128 * 40];   // 128 rows x 32 cols (pad 40)
    __shared__ __align__(128) float sB[32 * 132];   // 32 rows x 128 cols (pad 132)
    __shared__ __align__(128) float sC[8 * 16 * 20];// per-warp 16x16 staging, ldm 20

    const int tid = threadIdx.x;
    const int warpId = tid >> 5, lane = tid & 31;
    const int wm = warpId >> 1;      // 0..3 -> 32-row slab
    const int wn = warpId & 1;       // 0..1 -> 64-col slab
    const int bm = blockIdx.x * 128;
    const int bn = blockIdx.y * 128;

    wmma::fragment<wmma::accumulator, 16, 16, 8, float> acc[2][4];
#pragma unroll
    for (int i = 0; i < 2; i++)
#pragma unroll
        for (int j = 0; j < 4; j++) wmma::fill_fragment(acc[i][j], 0.0f);

    for (int k0 = 0; k0 < K; k0 += 32) {
        // A tile: 128x32 floats as 1024 float4, 4 per thread
#pragma unroll
        for (int i = 0; i < 4; i++) {
            int v = tid + i * 256;
            int row = v >> 3, c4 = v & 7;
            float4 d = *(const float4*)(A + (size_t)(bm + row) * K + k0 + c4 * 4);
            *(float4*)(sA + row * 40 + c4 * 4) = d;
        }
        // B tile: 32x128 scalars (N may be unaligned), 16 per thread
#pragma unroll
        for (int i = 0; i < 16; i++) {
            int v = tid + i * 256;
            int kr = v >> 7, col = v & 127;
            int gc = bn + col;
            sB[kr * 132 + col] = (gc < N) ? B[(size_t)(k0 + kr) * N + gc] : 0.0f;
        }
        __syncthreads();

#pragma unroll
        for (int kk = 0; kk < 32; kk += 8) {
            wmma::fragment<wmma::matrix_a, 16, 16, 8, wmma::precision::tf32, wmma::row_major> ah[2], al[2];
#pragma unroll
            for (int i = 0; i < 2; i++) {
                wmma::load_matrix_sync(ah[i], sA + (wm * 32 + i * 16) * 40 + kk, 40);
#pragma unroll
                for (int e = 0; e < ah[i].num_elements; e++) {
                    float orig = ah[i].x[e];
                    float hi = wmma::__float_to_tf32(orig);
                    ah[i].x[e] = hi;
                    al[i].x[e] = wmma::__float_to_tf32(orig - hi);
                }
            }
#pragma unroll
            for (int j = 0; j < 4; j++) {
                wmma::fragment<wmma::matrix_b, 16, 16, 8, wmma::precision::tf32, wmma::row_major> bh, bl;
                wmma::load_matrix_sync(bh, sB + kk * 132 + wn * 64 + j * 16, 132);
#pragma unroll
                for (int e = 0; e < bh.num_elements; e++) {
                    float orig = bh.x[e];
                    float hi = wmma::__float_to_tf32(orig);
                    bh.x[e] = hi;
                    bl.x[e] = wmma::__float_to_tf32(orig - hi);
                }
#pragma unroll
                for (int i = 0; i < 2; i++) {
                    wmma::mma_sync(acc[i][j], ah[i], bl, acc[i][j]);
                    wmma::mma_sync(acc[i][j], al[i], bh, acc[i][j]);
                    wmma::mma_sync(acc[i][j], ah[i], bh, acc[i][j]);
                }
            }
        }
        __syncthreads();
    }

    // epilogue via per-warp smem staging (guarded N, epilogue ops); ldm=20 (mult of 4)
    float* sc = sC + warpId * 320;
#pragma unroll
    for (int i = 0; i < 2; i++) {
#pragma unroll
        for (int j = 0; j < 4; j++) {
            wmma::store_matrix_sync(sc, acc[i][j], 20, wmma::mem_row_major);
            __syncwarp();
#pragma unroll
            for (int e = lane; e < 256; e += 32) {
                int r = e >> 4, c = e & 15;
                int gr = bm + wm * 32 + i * 16 + r;
                int gc = bn + wn * 64 + j * 16 + c;
                if (gc < N) {
                    float v = sc[r * 20 + c];
                    if (mode == 1)      v += bias[gc];
                    else if (mode == 2) v += addsrc[(size_t)gr * N + gc];
                    C[(size_t)gr * N + gc] = v;
                }
            }
            __syncwarp();
        }
    }
}

// ---------------- K2: depthwise causal conv4 + temb + silu + layernorm ------
__global__ void conv_silu_ln_kernel(const float* __restrict__ proj,
                                    const int* __restrict__ t,
                                    const float* __restrict__ temb,
                                    const float* __restrict__ cw,
                                    const float* __restrict__ cb,
                                    const float* __restrict__ g,
                                    const float* __restrict__ bb,
                                    float* __restrict__ xc_out) {
    __shared__ float ssum[8], ssq[8];
    int bs = blockIdx.x;
    int b = bs >> 10;
    int s = bs & (SS - 1);
    const float* te = temb + (size_t)t[b] * DII;

    float vals[4];
    float lsum = 0.f, lsq = 0.f;
#pragma unroll
    for (int u = 0; u < 4; u++) {
        int di = threadIdx.x + u * 256;
        float acc = cb[di];
        float tv = te[di];
        const float* w = cw + di * 4;
#pragma unroll
        for (int k = 0; k < 4; k++) {
            int sp = s - 3 + k;
            if (sp >= 0)
                acc += (proj[((size_t)(b * SS + sp)) * (2 * DII) + di] + tv) * w[k];
        }
        float v = silu_f(acc);
        vals[u] = v;
        lsum += v; lsq += v * v;
    }
    int wid = threadIdx.x >> 5, lane = threadIdx.x & 31;
    lsum = warp_sum(lsum);
    lsq  = warp_sum(lsq);
    if (lane == 0) { ssum[wid] = lsum; ssq[wid] = lsq; }
    __syncthreads();
    float tot = 0.f, totq = 0.f;
#pragma unroll
    for (int w = 0; w < 8; w++) { tot += ssum[w]; totq += ssq[w]; }
    float mu = tot * (1.0f / DII);
    float var = totq * (1.0f / DII) - mu * mu;
    float rstd = rsqrtf(var + 1e-5f);
#pragma unroll
    for (int u = 0; u < 4; u++) {
        int di = threadIdx.x + u * 256;
        xc_out[(size_t)bs * DII + di] = (vals[u] - mu) * rstd * g[di] + bb[di];
    }
}

// ---------------- K3: xproj GEMM (N=48) + dt/ad/bd/c coefficient prep -------
// one block handles 8 consecutive (b,s) rows; 128 threads
__global__ void prep_kernel(const float* __restrict__ xc,
                            const float* __restrict__ Wx,    // [1024,48]
                            const float* __restrict__ dtw,   // [16,16]
                            const float* __restrict__ dtb,   // [16]
                            const float* __restrict__ alog,  // [16]
                            float* __restrict__ coeff) {
    __shared__ __align__(16) float xr[8 * DII];   // 32 KB
    __shared__ float p_s[8][48];
    __shared__ float xnorm_s[8];

    int blk = blockIdx.x, tid = threadIdx.x;
    const float4* s4 = (const float4*)(xc + (size_t)blk * 8 * DII);
    float4* d4 = (float4*)xr;
    for (int i = tid; i < (8 * DII) / 4; i += 128) d4[i] = s4[i];
    __syncthreads();

    if (tid < 96) {
        int r2 = tid / 48, j = tid % 48;
        float a0 = 0.f, a1 = 0.f, a2 = 0.f, a3 = 0.f;
        const float* x0 = xr + r2 * DII;
#pragma unroll 4
        for (int l = 0; l < DII; l++) {
            float w = Wx[l * 48 + j];
            a0 += x0[l] * w;
            a1 += x0[l + 2 * DII] * w;
            a2 += x0[l + 4 * DII] * w;
            a3 += x0[l + 6 * DII] * w;
        }
        p_s[r2][j] = a0; p_s[r2 + 2][j] = a1; p_s[r2 + 4][j] = a2; p_s[r2 + 6][j] = a3;
    }
    // xnorm for rows wid and wid+4 (4 warps)
    {
        int wid = tid >> 5, lane = tid & 31;
        float s1 = 0.f, s2 = 0.f;
        for (int i = lane; i < DII; i += 32) {
            float v = xr[wid * DII + i];         s1 += v * v;
            float u = xr[(wid + 4) * DII + i];   s2 += u * u;
        }
        s1 = warp_sum(s1); s2 = warp_sum(s2);
        if (lane == 0) {
            xnorm_s[wid]     = fminf(sqrtf(s1), 1.0f);
            xnorm_s[wid + 4] = fminf(sqrtf(s2), 1.0f);
        }
    }
    __syncthreads();
    {
        int r = tid >> 4, i = tid & 15;   // 8 rows x 16 states
        float acc = dtb[i];
#pragma unroll
        for (int j = 0; j < 16; j++) acc += p_s[r][32 + j] * dtw[i * 16 + j];
        float dt = tanhf(acc) * 0.01f;
        float ad = 1.0f + dt * (-tanhf(alog[i]));
        size_t base = ((size_t)blk * 8 + r) * 48;
        coeff[base + i]      = ad;                       // a_disc
        coeff[base + 16 + i] = p_s[r][i] * xnorm_s[r];   // b_disc
        coeff[base + 32 + i] = p_s[r][16 + i];           // c
    }
}

// ---------------- K4: sequential SSM scan + gate fusion ---------------------
// grid = B * (DI/128); one thread per (b, di); 16-state recurrence in regs
__global__ void scan_kernel(const float* __restrict__ xc,
                            const float* __restrict__ coeff,
                            const float* __restrict__ proj,   // gate at cols [DI,2DI)
                            const float* __restrict__ dparam,
                            float* __restrict__ yg) {
    int b  = blockIdx.x >> 3;
    int di = ((blockIdx.x & 7) << 7) + threadIdx.x;

    float h[16];
#pragma unroll
    for (int k = 0; k < 16; k++) h[k] = 0.0f;
    float dp = dparam[di];

    const float*  xrow = xc   + (size_t)b * SS * DII + di;
    const float*  grow = proj + (size_t)b * SS * (2 * DII) + DII + di;
    float*        orow = yg   + (size_t)b * SS * DII + di;
    const float4* cf   = (const float4*)(coeff + (size_t)b * SS * 48);

    for (int tt = 0; tt < SS; tt++) {
        float ad[16], bd[16], cc[16];
#pragma unroll
        for (int q = 0; q < 4; q++) {
            ((float4*)ad)[q] = __ldg(&cf[q]);
            ((float4*)bd)[q] = __ldg(&cf[4 + q]);
            ((float4*)cc)[q] = __ldg(&cf[8 + q]);
        }
        cf += 12;
        float xv = __ldg(xrow); xrow += DII;
        float y = dp * xv;
#pragma unroll
        for (int k = 0; k < 16; k++) {
            float hn = h[k] * ad[k] + bd[k] * xv;
            hn = fminf(fmaxf(hn, -10.0f), 10.0f);
            h[k] = hn;
            y += cc[k] * hn;
        }
        float gv = __ldg(grow); grow += 2 * DII;
        orow[0] = y * silu_f(gv); orow += DII;
    }
}

// ---------------- orchestration ---------------------------------------------
extern "C" void kernel_launch(void* const* d_in, const int* in_sizes, int n_in,
                              void* d_out, int out_size) {
    (void)in_sizes; (void)n_in; (void)out_size;
    const int*   x        = (const int*)  d_in[0];
    const int*   t        = (const int*)  d_in[1];
    const float* emb      = (const float*)d_in[2];
    const float* pos      = (const float*)d_in[3];
    const float* temb     = (const float*)d_in[4];
    const float* in_w     = (const float*)d_in[5];
    const float* conv_w   = (const float*)d_in[6];
    const float* conv_b   = (const float*)d_in[7];
    const float* ln_g     = (const float*)d_in[8];
    const float* ln_b     = (const float*)d_in[9];
    const float* xproj_w  = (const float*)d_in[10];
    const float* dt_w     = (const float*)d_in[11];
    const float* dt_b     = (const float*)d_in[12];
    const float* a_log    = (const float*)d_in[13];
    const float* d_param  = (const float*)d_in[14];
    const float* out_pw   = (const float*)d_in[15];
    const float* out_w    = (const float*)d_in[16];
    const float* out_b    = (const float*)d_in[17];
    float* out = (float*)d_out;

    static float *p_h = nullptr, *p_proj = nullptr, *p_xc = nullptr,
                 *p_coeff = nullptr, *p_yg = nullptr;
    if (!p_h) {
        cudaGetSymbolAddress((void**)&p_h, g_h);
        cudaGetSymbolAddress((void**)&p_proj, g_proj);
        cudaGetSymbolAddress((void**)&p_xc, g_xc);
        cudaGetSymbolAddress((void**)&p_coeff, g_coeff);
        cudaGetSymbolAddress((void**)&p_yg, g_yg);
    }

    embed_kernel<<<BSS, 128>>>(x, emb, pos, p_h);

    for (int l = 0; l < NL; l++) {
        // proj = h @ in_w[l]   (2048 x 2048, K=512)
        gemm_tf32x3<<<dim3(BSS / 128, (2 * DII) / 128), 256>>>(
            p_h, in_w + (size_t)l * DD * 2 * DII, p_proj,
            BSS, 2 * DII, DD, nullptr, nullptr, 0);

        // xc = layernorm(silu(conv(proj[:, :DI] + temb)))
        conv_silu_ln_kernel<<<BSS, 256>>>(
            p_proj, t, temb,
            conv_w + (size_t)l * DII * 4, conv_b + (size_t)l * DII,
            ln_g + (size_t)l * DII, ln_b + (size_t)l * DII, p_xc);

        // coefficient prep: p = xc @ xproj_w, dt/ad/bd/c
        prep_kernel<<<BSS / 8, 128>>>(
            p_xc, xproj_w + (size_t)l * DII * 48,
            dt_w + (size_t)l * DSS * DSS, dt_b + (size_t)l * DSS,
            a_log + (size_t)l * DSS, p_coeff);

        // sequential scan + gate
        scan_kernel<<<BB * (DII / 128), 128>>>(
            p_xc, p_coeff, p_proj, d_param + (size_t)l * DII, p_yg);

        // h += yg @ out_proj_w[l]   (2048 x 512, K=1024), residual accumulate
        gemm_tf32x3<<<dim3(BSS / 128, DD / 128), 256>>>(
            p_yg, out_pw + (size_t)l * DII * DD, p_h,
            BSS, DD, DII, nullptr, p_h, 2);
    }

    // logits = h @ out_w + out_b   (2048 x 50257, K=512)
    gemm_tf32x3<<<dim3(BSS / 128, (VV + 127) / 128), 256>>>(
        p_h, out_w, out, BSS, VV, DD, out_b, nullptr, 1);
}

// round 3
// speedup vs baseline: 1.2350x; 1.2350x over previous
#include <cuda_runtime.h>
#include <cuda_bf16.h>
#include <mma.h>
#include <math.h>

using namespace nvcuda;

#define NL 4
#define DD 512
#define DII 1024
#define DSS 16
#define VV 50257
#define BB 2
#define SS 1024
#define BSS 2048   /* BB*SS */

// ---------------- scratch (static device globals; no allocations) ----------
__device__ __align__(256) float g_h[BSS * DD];          // 4 MB
__device__ __align__(256) float g_proj[BSS * 2 * DII];  // 16 MB
__device__ __align__(256) float g_xc[BSS * DII];        // 8 MB
__device__ __align__(256) float g_coeff[BSS * 48];      // 384 KB (ad|bd|c)
__device__ __align__(256) float g_yg[BSS * DII];        // 8 MB
__device__ __align__(256) float g_pbuf[BSS * 48];       // xproj output
__device__ __align__(256) float g_xnorm[BSS];           // per-token clipped norm

// ---------------- helpers ---------------------------------------------------
__device__ __forceinline__ float warp_sum(float v) {
#pragma unroll
    for (int o = 16; o > 0; o >>= 1) v += __shfl_xor_sync(0xffffffffu, v, o);
    return v;
}

__device__ __forceinline__ float silu_f(float x) {
    return x * (1.0f / (1.0f + __expf(-x)));
}

__device__ __forceinline__ float to_tf32(float x) {
    return wmma::__float_to_tf32(x);
}

// ---------------- K0: embedding gather + pos --------------------------------
__global__ void embed_kernel(const int* __restrict__ x, const float* __restrict__ emb,
                             const float* __restrict__ pos, float* __restrict__ h) {
    int bs = blockIdx.x;
    int s  = bs & (SS - 1);
    int tok = x[bs];
    const float4* e4 = (const float4*)(emb + (size_t)tok * DD);
    const float4* p4 = (const float4*)(pos + (size_t)s * DD);
    float4* h4 = (float4*)(h + (size_t)bs * DD);
    int i = threadIdx.x;           // 128 threads, 128 float4 = 512 floats
    float4 a = e4[i], p = p4[i];
    h4[i] = make_float4(a.x + p.x, a.y + p.y, a.z + p.z, a.w + p.w);
}

// ---------------- GEMM: tf32, NSPLIT=3 (fp32-accurate) or 1 (fast) ----------
// C[M,N] = A[M,K] @ B[K,N]; mode 0: plain, 1: +bias[n], 2: += addsrc[m,n]
// A,B row-major fp32. M % 128 == 0, K % 32 == 0; N arbitrary (guarded).
// hi/lo split precomputed in shared memory; next K-tile prefetched to regs.
template<int NSPLIT>
__global__ __launch_bounds__(256)
void gemm_tf32(const float* __restrict__ A, const float* __restrict__ B,
               float* __restrict__ C, int M, int N, int K,
               const float* __restrict__ bias, const float* __restrict__ addsrc,
               int mode) {
    extern __shared__ __align__(128) float ds[];
    float* sAhi = ds;                                       // 128 x 32 (stride 40)
    float* sAlo = (NSPLIT == 3) ? sAhi + 128 * 40 : sAhi;
    float* sBhi = (NSPLIT == 3) ? sAhi + 2 * 128 * 40 : sAhi + 128 * 40; // 32 x 128 (stride 132)
    float* sBlo = (NSPLIT == 3) ? sBhi + 32 * 132 : sBhi;
    __shared__ __align__(128) float sC[8 * 16 * 20];        // per-warp staging, ldm 20

    const int tid = threadIdx.x;
    const int warpId = tid >> 5, lane = tid & 31;
    const int wm = warpId >> 1;      // 0..3 -> 32-row slab
    const int wn = warpId & 1;       // 0..1 -> 64-col slab
    const int bm = blockIdx.x * 128;
    const int bn = blockIdx.y * 128;

    wmma::fragment<wmma::accumulator, 16, 16, 8, float> acc[2][4];
#pragma unroll
    for (int i = 0; i < 2; i++)
#pragma unroll
        for (int j = 0; j < 4; j++) wmma::fill_fragment(acc[i][j], 0.0f);

    float4 ra[4];
    float  rb[16];

    // prefetch tile 0
#pragma unroll
    for (int i = 0; i < 4; i++) {
        int v = tid + i * 256;
        int row = v >> 3, c4 = v & 7;
        ra[i] = *(const float4*)(A + (size_t)(bm + row) * K + c4 * 4);
    }
#pragma unroll
    for (int i = 0; i < 16; i++) {
        int v = tid + i * 256;
        int kr = v >> 7, col = v & 127;
        int gc = bn + col;
        rb[i] = (gc < N) ? B[(size_t)kr * N + gc] : 0.0f;
    }

    for (int k0 = 0; k0 < K; k0 += 32) {
        // split + store staged regs to smem
#pragma unroll
        for (int i = 0; i < 4; i++) {
            int v = tid + i * 256;
            int row = v >> 3, c4 = v & 7;
            float4 d = ra[i];
            float4 hi;
            hi.x = to_tf32(d.x); hi.y = to_tf32(d.y);
            hi.z = to_tf32(d.z); hi.w = to_tf32(d.w);
            *(float4*)(sAhi + row * 40 + c4 * 4) = hi;
            if (NSPLIT == 3) {
                float4 lo;
                lo.x = to_tf32(d.x - hi.x); lo.y = to_tf32(d.y - hi.y);
                lo.z = to_tf32(d.z - hi.z); lo.w = to_tf32(d.w - hi.w);
                *(float4*)(sAlo + row * 40 + c4 * 4) = lo;
            }
        }
#pragma unroll
        for (int i = 0; i < 16; i++) {
            int v = tid + i * 256;
            int kr = v >> 7, col = v & 127;
            float x = rb[i];
            float hi = to_tf32(x);
            sBhi[kr * 132 + col] = hi;
            if (NSPLIT == 3) sBlo[kr * 132 + col] = to_tf32(x - hi);
        }
        __syncthreads();

        // prefetch next tile while MMAs run
        if (k0 + 32 < K) {
            int kn = k0 + 32;
#pragma unroll
            for (int i = 0; i < 4; i++) {
                int v = tid + i * 256;
                int row = v >> 3, c4 = v & 7;
                ra[i] = *(const float4*)(A + (size_t)(bm + row) * K + kn + c4 * 4);
            }
#pragma unroll
            for (int i = 0; i < 16; i++) {
                int v = tid + i * 256;
                int kr = v >> 7, col = v & 127;
                int gc = bn + col;
                rb[i] = (gc < N) ? B[(size_t)(kn + kr) * N + gc] : 0.0f;
            }
        }

#pragma unroll
        for (int kk = 0; kk < 32; kk += 8) {
            wmma::fragment<wmma::matrix_a, 16, 16, 8, wmma::precision::tf32, wmma::row_major> ah[2], al[2];
#pragma unroll
            for (int i = 0; i < 2; i++) {
                wmma::load_matrix_sync(ah[i], sAhi + (wm * 32 + i * 16) * 40 + kk, 40);
                if (NSPLIT == 3)
                    wmma::load_matrix_sync(al[i], sAlo + (wm * 32 + i * 16) * 40 + kk, 40);
            }
#pragma unroll
            for (int j = 0; j < 4; j++) {
                wmma::fragment<wmma::matrix_b, 16, 16, 8, wmma::precision::tf32, wmma::row_major> bh, bl;
                wmma::load_matrix_sync(bh, sBhi + kk * 132 + wn * 64 + j * 16, 132);
                if (NSPLIT == 3)
                    wmma::load_matrix_sync(bl, sBlo + kk * 132 + wn * 64 + j * 16, 132);
#pragma unroll
                for (int i = 0; i < 2; i++) {
                    if (NSPLIT == 3) {
                        wmma::mma_sync(acc[i][j], ah[i], bl, acc[i][j]);
                        wmma::mma_sync(acc[i][j], al[i], bh, acc[i][j]);
                    }
                    wmma::mma_sync(acc[i][j], ah[i], bh, acc[i][j]);
                }
            }
        }
        __syncthreads();
    }

    // epilogue via per-warp smem staging (guarded N, epilogue ops); ldm=20
    float* sc = sC + warpId * 320;
#pragma unroll
    for (int i = 0; i < 2; i++) {
#pragma unroll
        for (int j = 0; j < 4; j++) {
            wmma::store_matrix_sync(sc, acc[i][j], 20, wmma::mem_row_major);
            __syncwarp();
#pragma unroll
            for (int e = lane; e < 256; e += 32) {
                int r = e >> 4, c = e & 15;
                int gr = bm + wm * 32 + i * 16 + r;
                int gc = bn + wn * 64 + j * 16 + c;
                if (gc < N) {
                    float v = sc[r * 20 + c];
                    if (mode == 1)      v += bias[gc];
                    else if (mode == 2) v += addsrc[(size_t)gr * N + gc];
                    C[(size_t)gr * N + gc] = v;
                }
            }
            __syncwarp();
        }
    }
}

// ---------------- K2: conv4 + temb + silu + layernorm + xnorm ---------------
__global__ void conv_silu_ln_kernel(const float* __restrict__ proj,
                                    const int* __restrict__ t,
                                    const float* __restrict__ temb,
                                    const float* __restrict__ cw,
                                    const float* __restrict__ cb,
                                    const float* __restrict__ g,
                                    const float* __restrict__ bb,
                                    float* __restrict__ xc_out,
                                    float* __restrict__ xnorm_out) {
    __shared__ float ssum[8], ssq[8];
    int bs = blockIdx.x;
    int b = bs >> 10;
    int s = bs & (SS - 1);
    const float* te = temb + (size_t)t[b] * DII;

    float vals[4];
    float lsum = 0.f, lsq = 0.f;
#pragma unroll
    for (int u = 0; u < 4; u++) {
        int di = threadIdx.x + u * 256;
        float acc = cb[di];
        float tv = te[di];
        const float* w = cw + di * 4;
#pragma unroll
        for (int k = 0; k < 4; k++) {
            int sp = s - 3 + k;
            if (sp >= 0)
                acc += (proj[((size_t)(b * SS + sp)) * (2 * DII) + di] + tv) * w[k];
        }
        float v = silu_f(acc);
        vals[u] = v;
        lsum += v; lsq += v * v;
    }
    int wid = threadIdx.x >> 5, lane = threadIdx.x & 31;
    lsum = warp_sum(lsum);
    lsq  = warp_sum(lsq);
    if (lane == 0) { ssum[wid] = lsum; ssq[wid] = lsq; }
    __syncthreads();
    float tot = 0.f, totq = 0.f;
#pragma unroll
    for (int w = 0; w < 8; w++) { tot += ssum[w]; totq += ssq[w]; }
    float mu = tot * (1.0f / DII);
    float var = totq * (1.0f / DII) - mu * mu;
    float rstd = rsqrtf(var + 1e-5f);

    float nrm = 0.f;
#pragma unroll
    for (int u = 0; u < 4; u++) {
        int di = threadIdx.x + u * 256;
        float o = (vals[u] - mu) * rstd * g[di] + bb[di];
        xc_out[(size_t)bs * DII + di] = o;
        nrm += o * o;
    }
    __syncthreads();             // protect ssum reuse
    nrm = warp_sum(nrm);
    if (lane == 0) ssum[wid] = nrm;
    __syncthreads();
    if (threadIdx.x == 0) {
        float tn = 0.f;
#pragma unroll
        for (int w = 0; w < 8; w++) tn += ssum[w];
        xnorm_out[bs] = fminf(sqrtf(tn), 1.0f);
    }
}

// ---------------- K3b: coefficient prep from p = xc@Wx ----------------------
// p[row][0:16]=b_mat, [16:32]=c, [32:48]=dt_pre
__global__ void coeff_kernel(const float* __restrict__ p,
                             const float* __restrict__ xnorm,
                             const float* __restrict__ dtw,   // [16,16]
                             const float* __restrict__ dtb,   // [16]
                             const float* __restrict__ alog,  // [16]
                             float* __restrict__ coeff) {
    int row = blockIdx.x * 16 + (threadIdx.x >> 4);
    int i = threadIdx.x & 15;
    const float* pr = p + (size_t)row * 48;
    float acc = dtb[i];
#pragma unroll
    for (int j = 0; j < 16; j++) acc += pr[32 + j] * dtw[i * 16 + j];
    float dt = tanhf(acc) * 0.01f;
    float ad = 1.0f + dt * (-tanhf(alog[i]));
    size_t base = (size_t)row * 48;
    coeff[base + i]      = ad;
    coeff[base + 16 + i] = pr[i] * xnorm[row];
    coeff[base + 32 + i] = pr[16 + i];
}

// ---------------- K4: sequential SSM scan + gate (software pipelined) -------
// grid = B * (DI/32) = 64 blocks of 32 threads; one thread per (b,di)
__global__ void scan_kernel(const float* __restrict__ xc,
                            const float* __restrict__ coeff,
                            const float* __restrict__ proj,   // gate at cols [DI,2DI)
                            const float* __restrict__ dparam,
                            float* __restrict__ yg) {
    int blk = blockIdx.x;
    int b   = blk >> 5;
    int di  = ((blk & 31) << 5) + threadIdx.x;

    float h[16];
#pragma unroll
    for (int k = 0; k < 16; k++) h[k] = 0.0f;
    float dp = dparam[di];

    const float*  xrow = xc   + (size_t)b * SS * DII + di;
    const float*  grow = proj + (size_t)b * SS * (2 * DII) + DII + di;
    float*        orow = yg   + (size_t)b * SS * DII + di;
    const float4* cf   = (const float4*)(coeff + (size_t)b * SS * 48);

    float c0[48];
    float x0, g0;
#pragma unroll
    for (int q = 0; q < 12; q++) ((float4*)c0)[q] = __ldg(&cf[q]);
    x0 = __ldg(xrow);
    g0 = __ldg(grow);

    for (int tt = 0; tt < SS; tt++) {
        float c1[48];
        float x1 = 0.f, g1 = 0.f;
        if (tt + 1 < SS) {
            const float4* cf1 = cf + 12;
#pragma unroll
            for (int q = 0; q < 12; q++) ((float4*)c1)[q] = __ldg(&cf1[q]);
            x1 = __ldg(xrow + DII);
            g1 = __ldg(grow + 2 * DII);
        }
        float y = dp * x0;
#pragma unroll
        for (int k = 0; k < 16; k++) {
            float hn = h[k] * c0[k] + c0[16 + k] * x0;
            hn = fminf(fmaxf(hn, -10.0f), 10.0f);
            h[k] = hn;
            y += c0[32 + k] * hn;
        }
        orow[0] = y * silu_f(g0);
        orow += DII; xrow += DII; grow += 2 * DII; cf += 12;
#pragma unroll
        for (int q = 0; q < 48; q++) c0[q] = c1[q];
        x0 = x1; g0 = g1;
    }
}

// ---------------- orchestration ---------------------------------------------
#define SMEM_SPLIT3 ((2 * 128 * 40 + 2 * 32 * 132) * 4)
#define SMEM_SPLIT1 ((128 * 40 + 32 * 132) * 4)

extern "C" void kernel_launch(void* const* d_in, const int* in_sizes, int n_in,
                              void* d_out, int out_size) {
    (void)in_sizes; (void)n_in; (void)out_size;
    const int*   x        = (const int*)  d_in[0];
    const int*   t        = (const int*)  d_in[1];
    const float* emb      = (const float*)d_in[2];
    const float* pos      = (const float*)d_in[3];
    const float* temb     = (const float*)d_in[4];
    const float* in_w     = (const float*)d_in[5];
    const float* conv_w   = (const float*)d_in[6];
    const float* conv_b   = (const float*)d_in[7];
    const float* ln_g     = (const float*)d_in[8];
    const float* ln_b     = (const float*)d_in[9];
    const float* xproj_w  = (const float*)d_in[10];
    const float* dt_w     = (const float*)d_in[11];
    const float* dt_b     = (const float*)d_in[12];
    const float* a_log    = (const float*)d_in[13];
    const float* d_param  = (const float*)d_in[14];
    const float* out_pw   = (const float*)d_in[15];
    const float* out_w    = (const float*)d_in[16];
    const float* out_b    = (const float*)d_in[17];
    float* out = (float*)d_out;

    static float *p_h = nullptr, *p_proj = nullptr, *p_xc = nullptr,
                 *p_coeff = nullptr, *p_yg = nullptr, *p_p = nullptr, *p_xn = nullptr;
    if (!p_h) {
        cudaGetSymbolAddress((void**)&p_h, g_h);
        cudaGetSymbolAddress((void**)&p_proj, g_proj);
        cudaGetSymbolAddress((void**)&p_xc, g_xc);
        cudaGetSymbolAddress((void**)&p_coeff, g_coeff);
        cudaGetSymbolAddress((void**)&p_yg, g_yg);
        cudaGetSymbolAddress((void**)&p_p, g_pbuf);
        cudaGetSymbolAddress((void**)&p_xn, g_xnorm);
        cudaFuncSetAttribute(gemm_tf32<3>, cudaFuncAttributeMaxDynamicSharedMemorySize, SMEM_SPLIT3);
        cudaFuncSetAttribute(gemm_tf32<1>, cudaFuncAttributeMaxDynamicSharedMemorySize, SMEM_SPLIT1);
    }

    embed_kernel<<<BSS, 128>>>(x, emb, pos, p_h);

    for (int l = 0; l < NL; l++) {
        // proj = h @ in_w[l]   (2048 x 2048, K=512)
        gemm_tf32<3><<<dim3(BSS / 128, (2 * DII) / 128), 256, SMEM_SPLIT3>>>(
            p_h, in_w + (size_t)l * DD * 2 * DII, p_proj,
            BSS, 2 * DII, DD, nullptr, nullptr, 0);

        // xc = layernorm(silu(conv(proj[:, :DI] + temb))) + xnorm
        conv_silu_ln_kernel<<<BSS, 256>>>(
            p_proj, t, temb,
            conv_w + (size_t)l * DII * 4, conv_b + (size_t)l * DII,
            ln_g + (size_t)l * DII, ln_b + (size_t)l * DII, p_xc, p_xn);

        // p = xc @ xproj_w   (2048 x 48, K=1024)
        gemm_tf32<3><<<dim3(BSS / 128, 1), 256, SMEM_SPLIT3>>>(
            p_xc, xproj_w + (size_t)l * DII * 48, p_p,
            BSS, 48, DII, nullptr, nullptr, 0);

        // coefficients ad/bd/c
        coeff_kernel<<<BSS / 16, 256>>>(
            p_p, p_xn,
            dt_w + (size_t)l * DSS * DSS, dt_b + (size_t)l * DSS,
            a_log + (size_t)l * DSS, p_coeff);

        // sequential scan + gate
        scan_kernel<<<BB * (DII / 32), 32>>>(
            p_xc, p_coeff, p_proj, d_param + (size_t)l * DII, p_yg);

        // h += yg @ out_proj_w[l]   (2048 x 512, K=1024), residual accumulate
        gemm_tf32<3><<<dim3(BSS / 128, DD / 128), 256, SMEM_SPLIT3>>>(
            p_yg, out_pw + (size_t)l * DII * DD, p_h,
            BSS, DD, DII, nullptr, p_h, 2);
    }

    // logits = h @ out_w + out_b   (2048 x 50257, K=512) — tf32x1 fast path
    gemm_tf32<1><<<dim3(BSS / 128, (VV + 127) / 128), 256, SMEM_SPLIT1>>>(
        p_h, out_w, out, BSS, VV, DD, out_b, nullptr, 1);
}

// round 4
// speedup vs baseline: 1.7478x; 1.4153x over previous
#include <cuda_runtime.h>
#include <cuda_bf16.h>
#include <mma.h>
#include <math.h>

using namespace nvcuda;

#define NL 4
#define DD 512
#define DII 1024
#define DSS 16
#define VV 50257
#define BB 2
#define SS 1024
#define BSS 2048   /* BB*SS */

// ---------------- scratch (static device globals; no allocations) ----------
__device__ __align__(256) float g_h[BSS * DD];          // 4 MB
__device__ __align__(256) float g_proj[BSS * 2 * DII];  // 16 MB
__device__ __align__(256) float g_xc[BSS * DII];        // 8 MB
__device__ __align__(256) float g_coeff[BSS * 48];      // 384 KB (ad|bd|c)
__device__ __align__(256) float g_yg[BSS * DII];        // 8 MB
__device__ __align__(256) float g_pbuf[BSS * 48];       // xproj output
__device__ __align__(256) float g_xnorm[BSS];           // per-token clipped norm

// ---------------- helpers ---------------------------------------------------
__device__ __forceinline__ float warp_sum(float v) {
#pragma unroll
    for (int o = 16; o > 0; o >>= 1) v += __shfl_xor_sync(0xffffffffu, v, o);
    return v;
}

__device__ __forceinline__ float silu_f(float x) {
    return x * (1.0f / (1.0f + __expf(-x)));
}

__device__ __forceinline__ void split_bf16(float x, __nv_bfloat16& hi, __nv_bfloat16& lo) {
    hi = __float2bfloat16_rn(x);
    lo = __float2bfloat16_rn(x - __bfloat162float(hi));
}

// ---------------- K0: embedding gather + pos --------------------------------
__global__ void embed_kernel(const int* __restrict__ x, const float* __restrict__ emb,
                             const float* __restrict__ pos, float* __restrict__ h) {
    int bs = blockIdx.x;
    int s  = bs & (SS - 1);
    int tok = x[bs];
    const float4* e4 = (const float4*)(emb + (size_t)tok * DD);
    const float4* p4 = (const float4*)(pos + (size_t)s * DD);
    float4* h4 = (float4*)(h + (size_t)bs * DD);
    int i = threadIdx.x;           // 128 threads, 128 float4 = 512 floats
    float4 a = e4[i], p = p4[i];
    h4[i] = make_float4(a.x + p.x, a.y + p.y, a.z + p.z, a.w + p.w);
}

// ---------------- GEMM: bf16-split3 (hh + lh + hl), fp32 accumulate --------
// C[M,N] = A[M,K] @ B[K,N]; mode 0: plain, 1: +bias[n], 2: += addsrc[m,n]
// A,B row-major fp32. M % 128 == 0, K % 32 == 0; N arbitrary (guarded).
// hi/lo bf16 split done once at STS; next K-tile prefetched to registers.
__global__ __launch_bounds__(256)
void gemm_bf16s3(const float* __restrict__ A, const float* __restrict__ B,
                 float* __restrict__ C, int M, int N, int K,
                 const float* __restrict__ bias, const float* __restrict__ addsrc,
                 int mode) {
    __shared__ __align__(128) __nv_bfloat16 sAhi[128 * 40];   // 128 rows x 32 k (pad 40)
    __shared__ __align__(128) __nv_bfloat16 sAlo[128 * 40];
    __shared__ __align__(128) __nv_bfloat16 sBhi[32 * 136];   // 32 k x 128 cols (pad 136)
    __shared__ __align__(128) __nv_bfloat16 sBlo[32 * 136];
    __shared__ __align__(128) float sC[8 * 16 * 20];          // per-warp staging, ldm 20

    const int tid = threadIdx.x;
    const int warpId = tid >> 5, lane = tid & 31;
    const int wm = warpId >> 1;      // 0..3 -> 32-row slab
    const int wn = warpId & 1;       // 0..1 -> 64-col slab
    const int bm = blockIdx.x * 128;
    const int bn = blockIdx.y * 128;

    wmma::fragment<wmma::accumulator, 16, 16, 16, float> acc[2][4];
#pragma unroll
    for (int i = 0; i < 2; i++)
#pragma unroll
        for (int j = 0; j < 4; j++) wmma::fill_fragment(acc[i][j], 0.0f);

    float4 ra[4];     // A prefetch: 4 x float4 per thread = 128x32
    float2 rb[8];     // B prefetch: 8 x float2 per thread = 32x128

    // prefetch tile 0
#pragma unroll
    for (int i = 0; i < 4; i++) {
        int v = tid + i * 256;
        int row = v >> 3, c4 = v & 7;
        ra[i] = *(const float4*)(A + (size_t)(bm + row) * K + c4 * 4);
    }
#pragma unroll
    for (int i = 0; i < 8; i++) {
        int v = tid + i * 256;             // 0..2047 pairs
        int kr = v >> 6, cp = v & 63;
        int gc = bn + cp * 2;
        float2 d;
        d.x = (gc     < N) ? B[(size_t)kr * N + gc]     : 0.0f;
        d.y = (gc + 1 < N) ? B[(size_t)kr * N + gc + 1] : 0.0f;
        rb[i] = d;
    }

    for (int k0 = 0; k0 < K; k0 += 32) {
        // split + store staged regs to smem (bf16 hi/lo)
#pragma unroll
        for (int i = 0; i < 4; i++) {
            int v = tid + i * 256;
            int row = v >> 3, c4 = v & 7;
            float4 d = ra[i];
            __nv_bfloat16 h0, l0, h1, l1, h2, l2, h3, l3;
            split_bf16(d.x, h0, l0); split_bf16(d.y, h1, l1);
            split_bf16(d.z, h2, l2); split_bf16(d.w, h3, l3);
            __nv_bfloat162* ph = (__nv_bfloat162*)(sAhi + row * 40 + c4 * 4);
            __nv_bfloat162* pl = (__nv_bfloat162*)(sAlo + row * 40 + c4 * 4);
            ph[0] = __nv_bfloat162(h0, h1); ph[1] = __nv_bfloat162(h2, h3);
            pl[0] = __nv_bfloat162(l0, l1); pl[1] = __nv_bfloat162(l2, l3);
        }
#pragma unroll
        for (int i = 0; i < 8; i++) {
            int v = tid + i * 256;
            int kr = v >> 6, cp = v & 63;
            float2 d = rb[i];
            __nv_bfloat16 h0, l0, h1, l1;
            split_bf16(d.x, h0, l0); split_bf16(d.y, h1, l1);
            *(__nv_bfloat162*)(sBhi + kr * 136 + cp * 2) = __nv_bfloat162(h0, h1);
            *(__nv_bfloat162*)(sBlo + kr * 136 + cp * 2) = __nv_bfloat162(l0, l1);
        }
        __syncthreads();

        // prefetch next tile while MMAs run
        if (k0 + 32 < K) {
            int kn = k0 + 32;
#pragma unroll
            for (int i = 0; i < 4; i++) {
                int v = tid + i * 256;
                int row = v >> 3, c4 = v & 7;
                ra[i] = *(const float4*)(A + (size_t)(bm + row) * K + kn + c4 * 4);
            }
#pragma unroll
            for (int i = 0; i < 8; i++) {
                int v = tid + i * 256;
                int kr = v >> 6, cp = v & 63;
                int gc = bn + cp * 2;
                float2 d;
                d.x = (gc     < N) ? B[(size_t)(kn + kr) * N + gc]     : 0.0f;
                d.y = (gc + 1 < N) ? B[(size_t)(kn + kr) * N + gc + 1] : 0.0f;
                rb[i] = d;
            }
        }

#pragma unroll
        for (int kk = 0; kk < 32; kk += 16) {
            wmma::fragment<wmma::matrix_a, 16, 16, 16, __nv_bfloat16, wmma::row_major> ah[2], al[2];
#pragma unroll
            for (int i = 0; i < 2; i++) {
                wmma::load_matrix_sync(ah[i], sAhi + (wm * 32 + i * 16) * 40 + kk, 40);
                wmma::load_matrix_sync(al[i], sAlo + (wm * 32 + i * 16) * 40 + kk, 40);
            }
#pragma unroll
            for (int j = 0; j < 4; j++) {
                wmma::fragment<wmma::matrix_b, 16, 16, 16, __nv_bfloat16, wmma::row_major> bh, bl;
                wmma::load_matrix_sync(bh, sBhi + kk * 136 + wn * 64 + j * 16, 136);
                wmma::load_matrix_sync(bl, sBlo + kk * 136 + wn * 64 + j * 16, 136);
#pragma unroll
                for (int i = 0; i < 2; i++) {
                    wmma::mma_sync(acc[i][j], ah[i], bh, acc[i][j]);
                    wmma::mma_sync(acc[i][j], al[i], bh, acc[i][j]);
                    wmma::mma_sync(acc[i][j], ah[i], bl, acc[i][j]);
                }
            }
        }
        __syncthreads();
    }

    // epilogue via per-warp smem staging (guarded N, epilogue ops); ldm=20
    float* sc = sC + warpId * 320;
#pragma unroll
    for (int i = 0; i < 2; i++) {
#pragma unroll
        for (int j = 0; j < 4; j++) {
            wmma::store_matrix_sync(sc, acc[i][j], 20, wmma::mem_row_major);
            __syncwarp();
#pragma unroll
            for (int e = lane; e < 256; e += 32) {
                int r = e >> 4, c = e & 15;
                int gr = bm + wm * 32 + i * 16 + r;
                int gc = bn + wn * 64 + j * 16 + c;
                if (gc < N) {
                    float v = sc[r * 20 + c];
                    if (mode == 1)      v += bias[gc];
                    else if (mode == 2) v += addsrc[(size_t)gr * N + gc];
                    C[(size_t)gr * N + gc] = v;
                }
            }
            __syncwarp();
        }
    }
}

// ---------------- K2: conv4 + temb + silu + layernorm + xnorm ---------------
__global__ void conv_silu_ln_kernel(const float* __restrict__ proj,
                                    const int* __restrict__ t,
                                    const float* __restrict__ temb,
                                    const float* __restrict__ cw,
                                    const float* __restrict__ cb,
                                    const float* __restrict__ g,
                                    const float* __restrict__ bb,
                                    float* __restrict__ xc_out,
                                    float* __restrict__ xnorm_out) {
    __shared__ float ssum[8], ssq[8];
    int bs = blockIdx.x;
    int b = bs >> 10;
    int s = bs & (SS - 1);
    const float* te = temb + (size_t)t[b] * DII;

    float vals[4];
    float lsum = 0.f, lsq = 0.f;
#pragma unroll
    for (int u = 0; u < 4; u++) {
        int di = threadIdx.x + u * 256;
        float acc = cb[di];
        float tv = te[di];
        const float* w = cw + di * 4;
#pragma unroll
        for (int k = 0; k < 4; k++) {
            int sp = s - 3 + k;
            if (sp >= 0)
                acc += (proj[((size_t)(b * SS + sp)) * (2 * DII) + di] + tv) * w[k];
        }
        float v = silu_f(acc);
        vals[u] = v;
        lsum += v; lsq += v * v;
    }
    int wid = threadIdx.x >> 5, lane = threadIdx.x & 31;
    lsum = warp_sum(lsum);
    lsq  = warp_sum(lsq);
    if (lane == 0) { ssum[wid] = lsum; ssq[wid] = lsq; }
    __syncthreads();
    float tot = 0.f, totq = 0.f;
#pragma unroll
    for (int w = 0; w < 8; w++) { tot += ssum[w]; totq += ssq[w]; }
    float mu = tot * (1.0f / DII);
    float var = totq * (1.0f / DII) - mu * mu;
    float rstd = rsqrtf(var + 1e-5f);

    float nrm = 0.f;
#pragma unroll
    for (int u = 0; u < 4; u++) {
        int di = threadIdx.x + u * 256;
        float o = (vals[u] - mu) * rstd * g[di] + bb[di];
        xc_out[(size_t)bs * DII + di] = o;
        nrm += o * o;
    }
    __syncthreads();             // protect ssum reuse
    nrm = warp_sum(nrm);
    if (lane == 0) ssum[wid] = nrm;
    __syncthreads();
    if (threadIdx.x == 0) {
        float tn = 0.f;
#pragma unroll
        for (int w = 0; w < 8; w++) tn += ssum[w];
        xnorm_out[bs] = fminf(sqrtf(tn), 1.0f);
    }
}

// ---------------- K3a: dedicated small-N xproj GEMM (2048 x 48, K=1024) -----
// 128 blocks x 256 threads; block = 16 rows; thread = (row, 3 cols)
__global__ __launch_bounds__(256)
void xproj_kernel(const float* __restrict__ xc, const float* __restrict__ Wx,
                  float* __restrict__ p) {
    __shared__ float sx[16][17];
    __shared__ float sw[16][49];
    int r  = threadIdx.x >> 4;          // 0..15
    int cl = (threadIdx.x & 15) * 3;    // 0,3,...,45
    size_t rowbase = (size_t)blockIdx.x * 16;
    float a0 = 0.f, a1 = 0.f, a2 = 0.f;

    for (int k0 = 0; k0 < DII; k0 += 16) {
        sx[threadIdx.x >> 4][threadIdx.x & 15] =
            xc[(rowbase + (threadIdx.x >> 4)) * DII + k0 + (threadIdx.x & 15)];
#pragma unroll
        for (int i = threadIdx.x; i < 16 * 48; i += 256)
            sw[i / 48][i % 48] = Wx[(size_t)(k0 + i / 48) * 48 + (i % 48)];
        __syncthreads();
#pragma unroll
        for (int kk = 0; kk < 16; kk++) {
            float xv = sx[r][kk];
            a0 += xv * sw[kk][cl];
            a1 += xv * sw[kk][cl + 1];
            a2 += xv * sw[kk][cl + 2];
        }
        __syncthreads();
    }
    float* pr = p + (rowbase + r) * 48 + cl;
    pr[0] = a0; pr[1] = a1; pr[2] = a2;
}

// ---------------- K3b: coefficient prep from p = xc@Wx ----------------------
// p[row][0:16]=b_mat, [16:32]=c, [32:48]=dt_pre
__global__ void coeff_kernel(const float* __restrict__ p,
                             const float* __restrict__ xnorm,
                             const float* __restrict__ dtw,   // [16,16]
                             const float* __restrict__ dtb,   // [16]
                             const float* __restrict__ alog,  // [16]
                             float* __restrict__ coeff) {
    int row = blockIdx.x * 16 + (threadIdx.x >> 4);
    int i = threadIdx.x & 15;
    const float* pr = p + (size_t)row * 48;
    float acc = dtb[i];
#pragma unroll
    for (int j = 0; j < 16; j++) acc += pr[32 + j] * dtw[i * 16 + j];
    float dt = tanhf(acc) * 0.01f;
    float ad = 1.0f + dt * (-tanhf(alog[i]));
    size_t base = (size_t)row * 48;
    coeff[base + i]      = ad;
    coeff[base + 16 + i] = pr[i] * xnorm[row];
    coeff[base + 32 + i] = pr[16 + i];
}

// ---------------- K4: sequential SSM scan + gate (software pipelined) -------
// grid = B * (DI/32) = 64 blocks of 32 threads; one thread per (b,di)
__global__ void scan_kernel(const float* __restrict__ xc,
                            const float* __restrict__ coeff,
                            const float* __restrict__ proj,   // gate at cols [DI,2DI)
                            const float* __restrict__ dparam,
                            float* __restrict__ yg) {
    int blk = blockIdx.x;
    int b   = blk >> 5;
    int di  = ((blk & 31) << 5) + threadIdx.x;

    float h[16];
#pragma unroll
    for (int k = 0; k < 16; k++) h[k] = 0.0f;
    float dp = dparam[di];

    const float*  xrow = xc   + (size_t)b * SS * DII + di;
    const float*  grow = proj + (size_t)b * SS * (2 * DII) + DII + di;
    float*        orow = yg   + (size_t)b * SS * DII + di;
    const float4* cf   = (const float4*)(coeff + (size_t)b * SS * 48);

    float c0[48];
    float x0, g0;
#pragma unroll
    for (int q = 0; q < 12; q++) ((float4*)c0)[q] = __ldg(&cf[q]);
    x0 = __ldg(xrow);
    g0 = __ldg(grow);

    for (int tt = 0; tt < SS; tt++) {
        float c1[48];
        float x1 = 0.f, g1 = 0.f;
        if (tt + 1 < SS) {
            const float4* cf1 = cf + 12;
#pragma unroll
            for (int q = 0; q < 12; q++) ((float4*)c1)[q] = __ldg(&cf1[q]);
            x1 = __ldg(xrow + DII);
            g1 = __ldg(grow + 2 * DII);
        }
        float y = dp * x0;
#pragma unroll
        for (int k = 0; k < 16; k++) {
            float hn = h[k] * c0[k] + c0[16 + k] * x0;
            hn = fminf(fmaxf(hn, -10.0f), 10.0f);
            h[k] = hn;
            y += c0[32 + k] * hn;
        }
        orow[0] = y * silu_f(g0);
        orow += DII; xrow += DII; grow += 2 * DII; cf += 12;
#pragma unroll
        for (int q = 0; q < 48; q++) c0[q] = c1[q];
        x0 = x1; g0 = g1;
    }
}

// ---------------- orchestration ---------------------------------------------
extern "C" void kernel_launch(void* const* d_in, const int* in_sizes, int n_in,
                              void* d_out, int out_size) {
    (void)in_sizes; (void)n_in; (void)out_size;
    const int*   x        = (const int*)  d_in[0];
    const int*   t        = (const int*)  d_in[1];
    const float* emb      = (const float*)d_in[2];
    const float* pos      = (const float*)d_in[3];
    const float* temb     = (const float*)d_in[4];
    const float* in_w     = (const float*)d_in[5];
    const float* conv_w   = (const float*)d_in[6];
    const float* conv_b   = (const float*)d_in[7];
    const float* ln_g     = (const float*)d_in[8];
    const float* ln_b     = (const float*)d_in[9];
    const float* xproj_w  = (const float*)d_in[10];
    const float* dt_w     = (const float*)d_in[11];
    const float* dt_b     = (const float*)d_in[12];
    const float* a_log    = (const float*)d_in[13];
    const float* d_param  = (const float*)d_in[14];
    const float* out_pw   = (const float*)d_in[15];
    const float* out_w    = (const float*)d_in[16];
    const float* out_b    = (const float*)d_in[17];
    float* out = (float*)d_out;

    static float *p_h = nullptr, *p_proj = nullptr, *p_xc = nullptr,
                 *p_coeff = nullptr, *p_yg = nullptr, *p_p = nullptr, *p_xn = nullptr;
    if (!p_h) {
        cudaGetSymbolAddress((void**)&p_h, g_h);
        cudaGetSymbolAddress((void**)&p_proj, g_proj);
        cudaGetSymbolAddress((void**)&p_xc, g_xc);
        cudaGetSymbolAddress((void**)&p_coeff, g_coeff);
        cudaGetSymbolAddress((void**)&p_yg, g_yg);
        cudaGetSymbolAddress((void**)&p_p, g_pbuf);
        cudaGetSymbolAddress((void**)&p_xn, g_xnorm);
    }

    embed_kernel<<<BSS, 128>>>(x, emb, pos, p_h);

    for (int l = 0; l < NL; l++) {
        // proj = h @ in_w[l]   (2048 x 2048, K=512)
        gemm_bf16s3<<<dim3(BSS / 128, (2 * DII) / 128), 256>>>(
            p_h, in_w + (size_t)l * DD * 2 * DII, p_proj,
            BSS, 2 * DII, DD, nullptr, nullptr, 0);

        // xc = layernorm(silu(conv(proj[:, :DI] + temb))) + xnorm
        conv_silu_ln_kernel<<<BSS, 256>>>(
            p_proj, t, temb,
            conv_w + (size_t)l * DII * 4, conv_b + (size_t)l * DII,
            ln_g + (size_t)l * DII, ln_b + (size_t)l * DII, p_xc, p_xn);

        // p = xc @ xproj_w   (2048 x 48, K=1024) — dedicated small-N kernel
        xproj_kernel<<<BSS / 16, 256>>>(
            p_xc, xproj_w + (size_t)l * DII * 48, p_p);

        // coefficients ad/bd/c
        coeff_kernel<<<BSS / 16, 256>>>(
            p_p, p_xn,
            dt_w + (size_t)l * DSS * DSS, dt_b + (size_t)l * DSS,
            a_log + (size_t)l * DSS, p_coeff);

        // sequential scan + gate
        scan_kernel<<<BB * (DII / 32), 32>>>(
            p_xc, p_coeff, p_proj, d_param + (size_t)l * DII, p_yg);

        // h += yg @ out_proj_w[l]   (2048 x 512, K=1024), residual accumulate
        gemm_bf16s3<<<dim3(BSS / 128, DD / 128), 256>>>(
            p_yg, out_pw + (size_t)l * DII * DD, p_h,
            BSS, DD, DII, nullptr, p_h, 2);
    }

    // logits = h @ out_w + out_b   (2048 x 50257, K=512)
    gemm_bf16s3<<<dim3(BSS / 128, (VV + 127) / 128), 256>>>(
        p_h, out_w, out, BSS, VV, DD, out_b, nullptr, 1);
}

// round 6
// speedup vs baseline: 2.5154x; 1.4392x over previous
#include <cuda_runtime.h>
#include <cuda_fp16.h>
#include <mma.h>
#include <math.h>
#include <stdint.h>

using namespace nvcuda;

#define NL 4
#define DD 512
#define DII 1024
#define DSS 16
#define VV 50257
#define BB 2
#define SS 1024
#define BSS 2048    /* BB*SS */
#define NPADV 50432 /* VV padded to 128 */

// ---------------- scratch (static device globals; no allocations) ----------
__device__ __align__(256) float g_h[BSS * DD];
__device__ __align__(256) float g_proj[BSS * 2 * DII];
__device__ __align__(256) float g_xc[BSS * DII];
__device__ __align__(256) float g_coeff[BSS * 48];
__device__ __align__(256) float g_yg[BSS * DII];
__device__ __align__(256) float g_pbuf[BSS * 48];
__device__ __align__(256) float g_xnorm[BSS];
// fp16 hi/lo staging for GEMMs
__device__ __align__(256) __half g_Ahi[BSS * DII];
__device__ __align__(256) __half g_Alo[BSS * DII];
__device__ __align__(256) __half g_Bhi[NPADV * DD];
__device__ __align__(256) __half g_Blo[NPADV * DD];

// ---------------- helpers ---------------------------------------------------
__device__ __forceinline__ float warp_sum(float v) {
#pragma unroll
    for (int o = 16; o > 0; o >>= 1) v += __shfl_xor_sync(0xffffffffu, v, o);
    return v;
}
__device__ __forceinline__ float silu_f(float x) {
    return x * (1.0f / (1.0f + __expf(-x)));
}
__device__ __forceinline__ void split_f16(float x, __half& hi, __half& lo) {
    hi = __float2half_rn(x);
    lo = __float2half_rn(x - __half2float(hi));
}
__device__ __forceinline__ uint32_t smem_u32(const void* p) {
    uint32_t a;
    asm("{ .reg .u64 t; cvta.to.shared.u64 t, %1; cvt.u32.u64 %0, t; }" : "=r"(a) : "l"(p));
    return a;
}
__device__ __forceinline__ void cp_async16(uint32_t dst, const void* src) {
    asm volatile("cp.async.cg.shared.global [%0], [%1], 16;" :: "r"(dst), "l"(src));
}
__device__ __forceinline__ void cp_commit() {
    asm volatile("cp.async.commit_group;" ::: "memory");
}
template<int N> __device__ __forceinline__ void cp_wait() {
    asm volatile("cp.async.wait_group %0;" :: "n"(N) : "memory");
}

// ---------------- K0: embedding gather + pos --------------------------------
__global__ void embed_kernel(const int* __restrict__ x, const float* __restrict__ emb,
                             const float* __restrict__ pos, float* __restrict__ h) {
    int bs = blockIdx.x;
    int s  = bs & (SS - 1);
    int tok = x[bs];
    const float4* e4 = (const float4*)(emb + (size_t)tok * DD);
    const float4* p4 = (const float4*)(pos + (size_t)s * DD);
    float4* h4 = (float4*)(h + (size_t)bs * DD);
    int i = threadIdx.x;
    float4 a = e4[i], p = p4[i];
    h4[i] = make_float4(a.x + p.x, a.y + p.y, a.z + p.z, a.w + p.w);
}

// ---------------- prepass: fp32 [M,K] -> fp16 hi/lo --------------------------
__global__ void splitA_kernel(const float* __restrict__ A,
                              __half* __restrict__ hi, __half* __restrict__ lo) {
    int i = blockIdx.x * 256 + threadIdx.x;          // per float4
    float4 v = ((const float4*)A)[i];
    __half h0, l0, h1, l1, h2, l2, h3, l3;
    split_f16(v.x, h0, l0); split_f16(v.y, h1, l1);
    split_f16(v.z, h2, l2); split_f16(v.w, h3, l3);
    ((__half2*)hi)[i * 2]     = __halves2half2(h0, h1);
    ((__half2*)hi)[i * 2 + 1] = __halves2half2(h2, h3);
    ((__half2*)lo)[i * 2]     = __halves2half2(l0, l1);
    ((__half2*)lo)[i * 2 + 1] = __halves2half2(l2, l3);
}

// ---------------- prepass: fp32 B[K,N] -> fp16 hi(/lo) [K,NPAD] (padded) ----
__global__ void splitB_kernel(const float* __restrict__ B,
                              __half* __restrict__ hi, __half* __restrict__ lo,
                              int K, int N, int NPAD) {
    int idx = blockIdx.x * 256 + threadIdx.x;        // per 4 outputs
    int k = idx / (NPAD >> 2);
    int n4 = (idx - k * (NPAD >> 2)) << 2;
    float v[4];
#pragma unroll
    for (int j = 0; j < 4; j++) {
        int n = n4 + j;
        v[j] = (n < N) ? __ldg(B + (size_t)k * N + n) : 0.0f;
    }
    __half h0, l0, h1, l1, h2, l2, h3, l3;
    split_f16(v[0], h0, l0); split_f16(v[1], h1, l1);
    split_f16(v[2], h2, l2); split_f16(v[3], h3, l3);
    size_t o = ((size_t)k * NPAD + n4) >> 1;
    ((__half2*)hi)[o]     = __halves2half2(h0, h1);
    ((__half2*)hi)[o + 1] = __halves2half2(h2, h3);
    if (lo) {
        ((__half2*)lo)[o]     = __halves2half2(l0, l1);
        ((__half2*)lo)[o + 1] = __halves2half2(l2, l3);
    }
}

// ---------------- GEMM: fp16 wmma, TERMS=3 (hh+lh+hl) or 2 (hh+lh) ----------
// C[M,N] = (Ahi+Alo)[M,K] @ Bhi(+Blo)[K,NPAD]; ldb = NPAD.
// mode 0: plain, 1: +bias[n], 2: += addsrc[m,n]. M%128==0, K%32==0.
// 3-stage cp.async pipeline; 128x128 block tile, 8 warps of 32x64.
#define STAGE3 37888
#define STAGE2 29184

template<int TERMS>
__global__ __launch_bounds__(256)
void gemm_f16(const __half* __restrict__ Ahi, const __half* __restrict__ Alo,
              const __half* __restrict__ Bhi, const __half* __restrict__ Blo,
              float* __restrict__ C, int M, int N, int ldb, int K,
              const float* __restrict__ bias, const float* __restrict__ addsrc,
              int mode) {
    constexpr int STAGE = (TERMS == 3) ? STAGE3 : STAGE2;
    extern __shared__ __align__(128) char dsm[];
    __shared__ __align__(128) float sC[8 * 16 * 20];

    const int tid = threadIdx.x;
    const int warpId = tid >> 5, lane = tid & 31;
    const int wm = warpId >> 1;        // 0..3 -> 32-row slab
    const int wn = warpId & 1;         // 0..1 -> 64-col slab
    const int bm = blockIdx.x * 128;
    const int bn = blockIdx.y * 128;
    const int KT = K >> 5;
    const uint32_t sbase = smem_u32(dsm);

    wmma::fragment<wmma::accumulator, 16, 16, 16, float> acc[2][4];
#pragma unroll
    for (int i = 0; i < 2; i++)
#pragma unroll
        for (int j = 0; j < 4; j++) wmma::fill_fragment(acc[i][j], 0.0f);

    // tile loader: A 128x32 hi/lo (stride 40 halves), B 32x128 hi(/lo) (stride 136)
    auto load_tile = [&](int kt) {
        const uint32_t base = sbase + (uint32_t)(kt % 3) * STAGE;
        const int k0 = kt << 5;
#pragma unroll
        for (int i = 0; i < 2; i++) {
            int idx = i * 256 + tid;
            int row = idx >> 2, c = idx & 3;
            uint32_t off = (uint32_t)(row * 40 + c * 8) * 2;
            size_t go = (size_t)(bm + row) * K + k0 + c * 8;
            cp_async16(base + off,         Ahi + go);
            cp_async16(base + 10240 + off, Alo + go);
        }
#pragma unroll
        for (int i = 0; i < 2; i++) {
            int idx = i * 256 + tid;
            int row = idx >> 4, c = idx & 15;
            uint32_t off = (uint32_t)(row * 136 + c * 8) * 2;
            size_t go = (size_t)(k0 + row) * ldb + bn + c * 8;
            cp_async16(base + 20480 + off, Bhi + go);
            if (TERMS == 3)
                cp_async16(base + 29184 + off, Blo + go);
        }
        cp_commit();
    };

    load_tile(0);
    if (KT > 1) load_tile(1);

    for (int kt = 0; kt < KT; kt++) {
        if (kt + 1 < KT) cp_wait<1>(); else cp_wait<0>();
        __syncthreads();
        if (kt + 2 < KT) load_tile(kt + 2);

        const __half* sA  = (const __half*)(dsm + (size_t)(kt % 3) * STAGE);
        const __half* sAl = sA + 5120;               // 10240 B
        const __half* sB  = sA + 10240;              // 20480 B
        const __half* sBl = sA + 14592;              // 29184 B

#pragma unroll
        for (int kk = 0; kk < 32; kk += 16) {
            wmma::fragment<wmma::matrix_a, 16, 16, 16, __half, wmma::row_major> ah[2], al[2];
#pragma unroll
            for (int i = 0; i < 2; i++) {
                wmma::load_matrix_sync(ah[i], sA  + (wm * 32 + i * 16) * 40 + kk, 40);
                wmma::load_matrix_sync(al[i], sAl + (wm * 32 + i * 16) * 40 + kk, 40);
            }
#pragma unroll
            for (int j = 0; j < 4; j++) {
                wmma::fragment<wmma::matrix_b, 16, 16, 16, __half, wmma::row_major> bh, bl;
                wmma::load_matrix_sync(bh, sB + kk * 136 + wn * 64 + j * 16, 136);
                if (TERMS == 3)
                    wmma::load_matrix_sync(bl, sBl + kk * 136 + wn * 64 + j * 16, 136);
#pragma unroll
                for (int i = 0; i < 2; i++) {
                    wmma::mma_sync(acc[i][j], ah[i], bh, acc[i][j]);
                    wmma::mma_sync(acc[i][j], al[i], bh, acc[i][j]);
                    if (TERMS == 3)
                        wmma::mma_sync(acc[i][j], ah[i], bl, acc[i][j]);
                }
            }
        }
        __syncthreads();
    }

    // epilogue via per-warp smem staging (guarded N, epilogue ops); ldm=20
    float* sc = sC + warpId * 320;
#pragma unroll
    for (int i = 0; i < 2; i++) {
#pragma unroll
        for (int j = 0; j < 4; j++) {
            wmma::store_matrix_sync(sc, acc[i][j], 20, wmma::mem_row_major);
            __syncwarp();
#pragma unroll
            for (int e = lane; e < 256; e += 32) {
                int r = e >> 4, c = e & 15;
                int gr = bm + wm * 32 + i * 16 + r;
                int gc = bn + wn * 64 + j * 16 + c;
                if (gc < N) {
                    float v = sc[r * 20 + c];
                    if (mode == 1)      v += bias[gc];
                    else if (mode == 2) v += addsrc[(size_t)gr * N + gc];
                    C[(size_t)gr * N + gc] = v;
                }
            }
            __syncwarp();
        }
    }
}

// ---------------- K2: conv4 + temb + silu + layernorm + xnorm ---------------
__global__ void conv_silu_ln_kernel(const float* __restrict__ proj,
                                    const int* __restrict__ t,
                                    const float* __restrict__ temb,
                                    const float* __restrict__ cw,
                                    const float* __restrict__ cb,
                                    const float* __restrict__ g,
                                    const float* __restrict__ bb,
                                    float* __restrict__ xc_out,
                                    float* __restrict__ xnorm_out) {
    __shared__ float ssum[8], ssq[8];
    int bs = blockIdx.x;
    int b = bs >> 10;
    int s = bs & (SS - 1);
    const float* te = temb + (size_t)t[b] * DII;

    float vals[4];
    float lsum = 0.f, lsq = 0.f;
#pragma unroll
    for (int u = 0; u < 4; u++) {
        int di = threadIdx.x + u * 256;
        float acc = cb[di];
        float tv = te[di];
        const float* w = cw + di * 4;
#pragma unroll
        for (int k = 0; k < 4; k++) {
            int sp = s - 3 + k;
            if (sp >= 0)
                acc += (proj[((size_t)(b * SS + sp)) * (2 * DII) + di] + tv) * w[k];
        }
        float v = silu_f(acc);
        vals[u] = v;
        lsum += v; lsq += v * v;
    }
    int wid = threadIdx.x >> 5, lane = threadIdx.x & 31;
    lsum = warp_sum(lsum);
    lsq  = warp_sum(lsq);
    if (lane == 0) { ssum[wid] = lsum; ssq[wid] = lsq; }
    __syncthreads();
    float tot = 0.f, totq = 0.f;
#pragma unroll
    for (int w = 0; w < 8; w++) { tot += ssum[w]; totq += ssq[w]; }
    float mu = tot * (1.0f / DII);
    float var = totq * (1.0f / DII) - mu * mu;
    float rstd = rsqrtf(var + 1e-5f);

    float nrm = 0.f;
#pragma unroll
    for (int u = 0; u < 4; u++) {
        int di = threadIdx.x + u * 256;
        float o = (vals[u] - mu) * rstd * g[di] + bb[di];
        xc_out[(size_t)bs * DII + di] = o;
        nrm += o * o;
    }
    __syncthreads();
    nrm = warp_sum(nrm);
    if (lane == 0) ssum[wid] = nrm;
    __syncthreads();
    if (threadIdx.x == 0) {
        float tn = 0.f;
#pragma unroll
        for (int w = 0; w < 8; w++) tn += ssum[w];
        xnorm_out[bs] = fminf(sqrtf(tn), 1.0f);
    }
}

// ---------------- K3b: coefficient prep -------------------------------------
__global__ void coeff_kernel(const float* __restrict__ p,
                             const float* __restrict__ xnorm,
                             const float* __restrict__ dtw,
                             const float* __restrict__ dtb,
                             const float* __restrict__ alog,
                             float* __restrict__ coeff) {
    int row = blockIdx.x * 16 + (threadIdx.x >> 4);
    int i = threadIdx.x & 15;
    const float* pr = p + (size_t)row * 48;
    float acc = dtb[i];
#pragma unroll
    for (int j = 0; j < 16; j++) acc += pr[32 + j] * dtw[i * 16 + j];
    float dt = tanhf(acc) * 0.01f;
    float ad = 1.0f + dt * (-tanhf(alog[i]));
    size_t base = (size_t)row * 48;
    coeff[base + i]      = ad;
    coeff[base + 16 + i] = pr[i] * xnorm[row];
    coeff[base + 32 + i] = pr[16 + i];
}

// ---------------- K4: sequential SSM scan + gate ----------------------------
__global__ void scan_kernel(const float* __restrict__ xc,
                            const float* __restrict__ coeff,
                            const float* __restrict__ proj,
                            const float* __restrict__ dparam,
                            float* __restrict__ yg) {
    int blk = blockIdx.x;
    int b   = blk >> 5;
    int di  = ((blk & 31) << 5) + threadIdx.x;

    float h[16];
#pragma unroll
    for (int k = 0; k < 16; k++) h[k] = 0.0f;
    float dp = dparam[di];

    const float*  xrow = xc   + (size_t)b * SS * DII + di;
    const float*  grow = proj + (size_t)b * SS * (2 * DII) + DII + di;
    float*        orow = yg   + (size_t)b * SS * DII + di;
    const float4* cf   = (const float4*)(coeff + (size_t)b * SS * 48);

    float c0[48];
    float x0, g0;
#pragma unroll
    for (int q = 0; q < 12; q++) ((float4*)c0)[q] = __ldg(&cf[q]);
    x0 = __ldg(xrow);
    g0 = __ldg(grow);

    for (int tt = 0; tt < SS; tt++) {
        float c1[48];
        float x1 = 0.f, g1 = 0.f;
        if (tt + 1 < SS) {
            const float4* cf1 = cf + 12;
#pragma unroll
            for (int q = 0; q < 12; q++) ((float4*)c1)[q] = __ldg(&cf1[q]);
            x1 = __ldg(xrow + DII);
            g1 = __ldg(grow + 2 * DII);
        }
        float y = dp * x0;
#pragma unroll
        for (int k = 0; k < 16; k++) {
            float hn = h[k] * c0[k] + c0[16 + k] * x0;
            hn = fminf(fmaxf(hn, -10.0f), 10.0f);
            h[k] = hn;
            y += c0[32 + k] * hn;
        }
        orow[0] = y * silu_f(g0);
        orow += DII; xrow += DII; grow += 2 * DII; cf += 12;
#pragma unroll
        for (int q = 0; q < 48; q++) c0[q] = c1[q];
        x0 = x1; g0 = g1;
    }
}

// ---------------- orchestration ---------------------------------------------
extern "C" void kernel_launch(void* const* d_in, const int* in_sizes, int n_in,
                              void* d_out, int out_size) {
    (void)in_sizes; (void)n_in; (void)out_size;
    const int*   x        = (const int*)  d_in[0];
    const int*   t        = (const int*)  d_in[1];
    const float* emb      = (const float*)d_in[2];
    const float* pos      = (const float*)d_in[3];
    const float* temb     = (const float*)d_in[4];
    const float* in_w     = (const float*)d_in[5];
    const float* conv_w   = (const float*)d_in[6];
    const float* conv_b   = (const float*)d_in[7];
    const float* ln_g     = (const float*)d_in[8];
    const float* ln_b     = (const float*)d_in[9];
    const float* xproj_w  = (const float*)d_in[10];
    const float* dt_w     = (const float*)d_in[11];
    const float* dt_b     = (const float*)d_in[12];
    const float* a_log    = (const float*)d_in[13];
    const float* d_param  = (const float*)d_in[14];
    const float* out_pw   = (const float*)d_in[15];
    const float* out_w    = (const float*)d_in[16];
    const float* out_b    = (const float*)d_in[17];
    float* out = (float*)d_out;

    static float *p_h = nullptr, *p_proj = nullptr, *p_xc = nullptr,
                 *p_coeff = nullptr, *p_yg = nullptr, *p_p = nullptr, *p_xn = nullptr;
    static __half *p_ahi = nullptr, *p_alo = nullptr, *p_bhi = nullptr, *p_blo = nullptr;
    if (!p_h) {
        cudaGetSymbolAddress((void**)&p_h, g_h);
        cudaGetSymbolAddress((void**)&p_proj, g_proj);
        cudaGetSymbolAddress((void**)&p_xc, g_xc);
        cudaGetSymbolAddress((void**)&p_coeff, g_coeff);
        cudaGetSymbolAddress((void**)&p_yg, g_yg);
        cudaGetSymbolAddress((void**)&p_p, g_pbuf);
        cudaGetSymbolAddress((void**)&p_xn, g_xnorm);
        cudaGetSymbolAddress((void**)&p_ahi, g_Ahi);
        cudaGetSymbolAddress((void**)&p_alo, g_Alo);
        cudaGetSymbolAddress((void**)&p_bhi, g_Bhi);
        cudaGetSymbolAddress((void**)&p_blo, g_Blo);
        cudaFuncSetAttribute(gemm_f16<3>, cudaFuncAttributeMaxDynamicSharedMemorySize, 3 * STAGE3);
        cudaFuncSetAttribute(gemm_f16<2>, cudaFuncAttributeMaxDynamicSharedMemorySize, 3 * STAGE2);
    }

    embed_kernel<<<BSS, 128>>>(x, emb, pos, p_h);

    for (int l = 0; l < NL; l++) {
        // proj = h @ in_w[l]   (M=2048, N=2048, K=512)
        splitA_kernel<<<(BSS * DD / 4) / 256, 256>>>(p_h, p_ahi, p_alo);
        splitB_kernel<<<(DD * 2 * DII / 4) / 256, 256>>>(
            in_w + (size_t)l * DD * 2 * DII, p_bhi, p_blo, DD, 2 * DII, 2 * DII);
        gemm_f16<3><<<dim3(BSS / 128, (2 * DII) / 128), 256, 3 * STAGE3>>>(
            p_ahi, p_alo, p_bhi, p_blo, p_proj, BSS, 2 * DII, 2 * DII, DD,
            nullptr, nullptr, 0);

        conv_silu_ln_kernel<<<BSS, 256>>>(
            p_proj, t, temb,
            conv_w + (size_t)l * DII * 4, conv_b + (size_t)l * DII,
            ln_g + (size_t)l * DII, ln_b + (size_t)l * DII, p_xc, p_xn);

        // p = xc @ xproj_w   (M=2048, N=48 pad 128, K=1024) via tensor GEMM
        splitA_kernel<<<(BSS * DII / 4) / 256, 256>>>(p_xc, p_ahi, p_alo);
        splitB_kernel<<<(DII * 128 / 4) / 256, 256>>>(
            xproj_w + (size_t)l * DII * 48, p_bhi, p_blo, DII, 48, 128);
        gemm_f16<3><<<dim3(BSS / 128, 1), 256, 3 * STAGE3>>>(
            p_ahi, p_alo, p_bhi, p_blo, p_p, BSS, 48, 128, DII,
            nullptr, nullptr, 0);

        coeff_kernel<<<BSS / 16, 256>>>(
            p_p, p_xn,
            dt_w + (size_t)l * DSS * DSS, dt_b + (size_t)l * DSS,
            a_log + (size_t)l * DSS, p_coeff);

        scan_kernel<<<BB * (DII / 32), 32>>>(
            p_xc, p_coeff, p_proj, d_param + (size_t)l * DII, p_yg);

        // h += yg @ out_proj_w[l]   (M=2048, N=512, K=1024)  (A split reuses xc's? no: yg)
        splitA_kernel<<<(BSS * DII / 4) / 256, 256>>>(p_yg, p_ahi, p_alo);
        splitB_kernel<<<(DII * DD / 4) / 256, 256>>>(
            out_pw + (size_t)l * DII * DD, p_bhi, p_blo, DII, DD, DD);
        gemm_f16<3><<<dim3(BSS / 128, DD / 128), 256, 3 * STAGE3>>>(
            p_ahi, p_alo, p_bhi, p_blo, p_h, BSS, DD, DD, DII,
            nullptr, p_h, 2);
    }

    // logits = h @ out_w + out_b  (M=2048, N=50257 pad 50432, K=512), split2
    splitA_kernel<<<(BSS * DD / 4) / 256, 256>>>(p_h, p_ahi, p_alo);
    splitB_kernel<<<(DD * NPADV / 4) / 256, 256>>>(
        out_w, p_bhi, nullptr, DD, VV, NPADV);
    gemm_f16<2><<<dim3(BSS / 128, NPADV / 128), 256, 3 * STAGE2>>>(
        p_ahi, p_alo, p_bhi, nullptr, out, BSS, VV, NPADV, DD,
        out_b, nullptr, 1);
}

// round 7
// speedup vs baseline: 2.8443x; 1.1308x over previous
#include <cuda_runtime.h>
#include <cuda_fp16.h>
#include <mma.h>
#include <math.h>
#include <stdint.h>

using namespace nvcuda;

#define NL 4
#define DD 512
#define DII 1024
#define DSS 16
#define VV 50257
#define BB 2
#define SS 1024
#define BSS 2048    /* BB*SS */
#define NPADV 50432 /* VV padded to 128 */

// ---------------- scratch (static device globals; no allocations) ----------
__device__ __align__(256) float g_h[BSS * DD];
__device__ __align__(256) float g_proj[BSS * 2 * DII];
__device__ __align__(256) float g_xc[BSS * DII];
__device__ __align__(256) float g_coeff[BSS * 48];
__device__ __align__(256) float g_yg[BSS * DII];
__device__ __align__(256) float g_xnorm[BSS];
__device__ __align__(256) float g_part[2 * BSS * DD];   // K-split partials (8 MB)
// fp16 hi/lo staging for GEMMs
__device__ __align__(256) __half g_Ahi[BSS * DII];
__device__ __align__(256) __half g_Alo[BSS * DII];
__device__ __align__(256) __half g_Bhi[NPADV * DD];
__device__ __align__(256) __half g_Blo[NPADV * DD];

// ---------------- helpers ---------------------------------------------------
__device__ __forceinline__ float warp_sum(float v) {
#pragma unroll
    for (int o = 16; o > 0; o >>= 1) v += __shfl_xor_sync(0xffffffffu, v, o);
    return v;
}
__device__ __forceinline__ float silu_f(float x) {
    return x * (1.0f / (1.0f + __expf(-x)));
}
__device__ __forceinline__ void split_f16(float x, __half& hi, __half& lo) {
    hi = __float2half_rn(x);
    lo = __float2half_rn(x - __half2float(hi));
}
__device__ __forceinline__ uint32_t smem_u32(const void* p) {
    uint32_t a;
    asm("{ .reg .u64 t; cvta.to.shared.u64 t, %1; cvt.u32.u64 %0, t; }" : "=r"(a) : "l"(p));
    return a;
}
__device__ __forceinline__ void cp_async16(uint32_t dst, const void* src) {
    asm volatile("cp.async.cg.shared.global [%0], [%1], 16;" :: "r"(dst), "l"(src));
}
__device__ __forceinline__ void cp_commit() {
    asm volatile("cp.async.commit_group;" ::: "memory");
}
template<int N> __device__ __forceinline__ void cp_wait() {
    asm volatile("cp.async.wait_group %0;" :: "n"(N) : "memory");
}

// ---------------- K0: embedding gather + pos --------------------------------
__global__ void embed_kernel(const int* __restrict__ x, const float* __restrict__ emb,
                             const float* __restrict__ pos, float* __restrict__ h) {
    int bs = blockIdx.x;
    int s  = bs & (SS - 1);
    int tok = x[bs];
    const float4* e4 = (const float4*)(emb + (size_t)tok * DD);
    const float4* p4 = (const float4*)(pos + (size_t)s * DD);
    float4* h4 = (float4*)(h + (size_t)bs * DD);
    int i = threadIdx.x;
    float4 a = e4[i], p = p4[i];
    h4[i] = make_float4(a.x + p.x, a.y + p.y, a.z + p.z, a.w + p.w);
}

// ---------------- prepass: fp32 [M,K] -> fp16 hi/lo --------------------------
__global__ void splitA_kernel(const float* __restrict__ A,
                              __half* __restrict__ hi, __half* __restrict__ lo) {
    int i = blockIdx.x * 256 + threadIdx.x;          // per float4
    float4 v = ((const float4*)A)[i];
    __half h0, l0, h1, l1, h2, l2, h3, l3;
    split_f16(v.x, h0, l0); split_f16(v.y, h1, l1);
    split_f16(v.z, h2, l2); split_f16(v.w, h3, l3);
    ((__half2*)hi)[i * 2]     = __halves2half2(h0, h1);
    ((__half2*)hi)[i * 2 + 1] = __halves2half2(h2, h3);
    ((__half2*)lo)[i * 2]     = __halves2half2(l0, l1);
    ((__half2*)lo)[i * 2 + 1] = __halves2half2(l2, l3);
}

// ---------------- prepass: fp32 B[K,N] -> fp16 hi(/lo) [K,NPAD] (padded) ----
__global__ void splitB_kernel(const float* __restrict__ B,
                              __half* __restrict__ hi, __half* __restrict__ lo,
                              int K, int N, int NPAD) {
    int idx = blockIdx.x * 256 + threadIdx.x;        // per 4 outputs
    int k = idx / (NPAD >> 2);
    int n4 = (idx - k * (NPAD >> 2)) << 2;
    float v[4];
#pragma unroll
    for (int j = 0; j < 4; j++) {
        int n = n4 + j;
        v[j] = (n < N) ? __ldg(B + (size_t)k * N + n) : 0.0f;
    }
    __half h0, l0, h1, l1, h2, l2, h3, l3;
    split_f16(v[0], h0, l0); split_f16(v[1], h1, l1);
    split_f16(v[2], h2, l2); split_f16(v[3], h3, l3);
    size_t o = ((size_t)k * NPAD + n4) >> 1;
    ((__half2*)hi)[o]     = __halves2half2(h0, h1);
    ((__half2*)hi)[o + 1] = __halves2half2(h2, h3);
    if (lo) {
        ((__half2*)lo)[o]     = __halves2half2(l0, l1);
        ((__half2*)lo)[o + 1] = __halves2half2(l2, l3);
    }
}

// ---------------- GEMM: fp16 wmma, TERMS=3 (hh+lh+hl) or 2 (hh+lh) ----------
// C[M,N] = (Ahi+Alo)[M,lda] @ Bhi(+Blo)[*,ldb]; Kloop columns per z-part.
// gridDim.z = K-split parts; parts write to C + z*M*N (caller passes mode 0).
// mode 0: plain, 1: +bias[n], 2: += addsrc[m,n]. M%128==0, Kloop%32==0.
// 2-stage cp.async pipeline, 2 CTAs/SM; 128x128 tile, 8 warps of 32x64.
#define STAGE3 37888
#define STAGE2 29184

template<int TERMS>
__global__ __launch_bounds__(256, 2)
void gemm_f16(const __half* __restrict__ Ahi, const __half* __restrict__ Alo,
              const __half* __restrict__ Bhi, const __half* __restrict__ Blo,
              float* __restrict__ C, int M, int N, int ldb, int lda, int Kloop,
              const float* __restrict__ bias, const float* __restrict__ addsrc,
              int mode) {
    constexpr int STAGE = (TERMS == 3) ? STAGE3 : STAGE2;
    extern __shared__ __align__(128) char dsm[];
    __shared__ __align__(128) float sC[8 * 16 * 20];

    const int tid = threadIdx.x;
    const int warpId = tid >> 5, lane = tid & 31;
    const int wm = warpId >> 1;        // 0..3 -> 32-row slab
    const int wn = warpId & 1;         // 0..1 -> 64-col slab
    const int bm = blockIdx.x * 128;
    const int bn = blockIdx.y * 128;
    const int koff = blockIdx.z * Kloop;
    const int KT = Kloop >> 5;
    const uint32_t sbase = smem_u32(dsm);
    if (blockIdx.z) C += (size_t)blockIdx.z * M * N;

    wmma::fragment<wmma::accumulator, 16, 16, 16, float> acc[2][4];
#pragma unroll
    for (int i = 0; i < 2; i++)
#pragma unroll
        for (int j = 0; j < 4; j++) wmma::fill_fragment(acc[i][j], 0.0f);

    // tile loader: A 128x32 hi/lo (stride 40 halves), B 32x128 hi(/lo) (stride 136)
    auto load_tile = [&](int kt) {
        const uint32_t base = sbase + (uint32_t)(kt & 1) * STAGE;
        const int k0 = koff + (kt << 5);
#pragma unroll
        for (int i = 0; i < 2; i++) {
            int idx = i * 256 + tid;
            int row = idx >> 2, c = idx & 3;
            uint32_t off = (uint32_t)(row * 40 + c * 8) * 2;
            size_t go = (size_t)(bm + row) * lda + k0 + c * 8;
            cp_async16(base + off,         Ahi + go);
            cp_async16(base + 10240 + off, Alo + go);
        }
#pragma unroll
        for (int i = 0; i < 2; i++) {
            int idx = i * 256 + tid;
            int row = idx >> 4, c = idx & 15;
            uint32_t off = (uint32_t)(row * 136 + c * 8) * 2;
            size_t go = (size_t)(k0 + row) * ldb + bn + c * 8;
            cp_async16(base + 20480 + off, Bhi + go);
            if (TERMS == 3)
                cp_async16(base + 29184 + off, Blo + go);
        }
        cp_commit();
    };

    load_tile(0);
    if (KT > 1) load_tile(1);

    for (int kt = 0; kt < KT; kt++) {
        if (kt + 1 < KT) cp_wait<1>(); else cp_wait<0>();
        __syncthreads();

        const __half* sA  = (const __half*)(dsm + (size_t)(kt & 1) * STAGE);
        const __half* sAl = sA + 5120;               // 10240 B
        const __half* sB  = sA + 10240;              // 20480 B
        const __half* sBl = sA + 14592;              // 29184 B

#pragma unroll
        for (int kk = 0; kk < 32; kk += 16) {
            wmma::fragment<wmma::matrix_a, 16, 16, 16, __half, wmma::row_major> ah[2], al[2];
#pragma unroll
            for (int i = 0; i < 2; i++) {
                wmma::load_matrix_sync(ah[i], sA  + (wm * 32 + i * 16) * 40 + kk, 40);
                wmma::load_matrix_sync(al[i], sAl + (wm * 32 + i * 16) * 40 + kk, 40);
            }
#pragma unroll
            for (int j = 0; j < 4; j++) {
                wmma::fragment<wmma::matrix_b, 16, 16, 16, __half, wmma::row_major> bh, bl;
                wmma::load_matrix_sync(bh, sB + kk * 136 + wn * 64 + j * 16, 136);
                if (TERMS == 3)
                    wmma::load_matrix_sync(bl, sBl + kk * 136 + wn * 64 + j * 16, 136);
#pragma unroll
                for (int i = 0; i < 2; i++) {
                    wmma::mma_sync(acc[i][j], ah[i], bh, acc[i][j]);
                    wmma::mma_sync(acc[i][j], al[i], bh, acc[i][j]);
                    if (TERMS == 3)
                        wmma::mma_sync(acc[i][j], ah[i], bl, acc[i][j]);
                }
            }
        }
        __syncthreads();                 // all reads of buffer done
        if (kt + 2 < KT) load_tile(kt + 2);
    }

    // epilogue via per-warp smem staging (guarded N, epilogue ops); ldm=20
    float* sc = sC + warpId * 320;
#pragma unroll
    for (int i = 0; i < 2; i++) {
#pragma unroll
        for (int j = 0; j < 4; j++) {
            wmma::store_matrix_sync(sc, acc[i][j], 20, wmma::mem_row_major);
            __syncwarp();
#pragma unroll
            for (int e = lane; e < 256; e += 32) {
                int r = e >> 4, c = e & 15;
                int gr = bm + wm * 32 + i * 16 + r;
                int gc = bn + wn * 64 + j * 16 + c;
                if (gc < N) {
                    float v = sc[r * 20 + c];
                    if (mode == 1)      v += bias[gc];
                    else if (mode == 2) v += addsrc[(size_t)gr * N + gc];
                    C[(size_t)gr * N + gc] = v;
                }
            }
            __syncwarp();
        }
    }
}

// ---------------- residual + K-split reduce: h += p0 + p1 -------------------
__global__ void resid_add_kernel(float* __restrict__ h,
                                 const float* __restrict__ p) {
    int i = blockIdx.x * 256 + threadIdx.x;
    float4 a = ((float4*)h)[i];
    float4 b = ((const float4*)p)[i];
    float4 c = ((const float4*)(p + (size_t)BSS * DD))[i];
    a.x += b.x + c.x; a.y += b.y + c.y; a.z += b.z + c.z; a.w += b.w + c.w;
    ((float4*)h)[i] = a;
}

// ---------------- K2: conv4 + temb + silu + layernorm + xnorm ---------------
__global__ void conv_silu_ln_kernel(const float* __restrict__ proj,
                                    const int* __restrict__ t,
                                    const float* __restrict__ temb,
                                    const float* __restrict__ cw,
                                    const float* __restrict__ cb,
                                    const float* __restrict__ g,
                                    const float* __restrict__ bb,
                                    float* __restrict__ xc_out,
                                    float* __restrict__ xnorm_out) {
    __shared__ float ssum[8], ssq[8];
    int bs = blockIdx.x;
    int b = bs >> 10;
    int s = bs & (SS - 1);
    const float* te = temb + (size_t)t[b] * DII;

    float vals[4];
    float lsum = 0.f, lsq = 0.f;
#pragma unroll
    for (int u = 0; u < 4; u++) {
        int di = threadIdx.x + u * 256;
        float acc = cb[di];
        float tv = te[di];
        const float* w = cw + di * 4;
#pragma unroll
        for (int k = 0; k < 4; k++) {
            int sp = s - 3 + k;
            if (sp >= 0)
                acc += (proj[((size_t)(b * SS + sp)) * (2 * DII) + di] + tv) * w[k];
        }
        float v = silu_f(acc);
        vals[u] = v;
        lsum += v; lsq += v * v;
    }
    int wid = threadIdx.x >> 5, lane = threadIdx.x & 31;
    lsum = warp_sum(lsum);
    lsq  = warp_sum(lsq);
    if (lane == 0) { ssum[wid] = lsum; ssq[wid] = lsq; }
    __syncthreads();
    float tot = 0.f, totq = 0.f;
#pragma unroll
    for (int w = 0; w < 8; w++) { tot += ssum[w]; totq += ssq[w]; }
    float mu = tot * (1.0f / DII);
    float var = totq * (1.0f / DII) - mu * mu;
    float rstd = rsqrtf(var + 1e-5f);

    float nrm = 0.f;
#pragma unroll
    for (int u = 0; u < 4; u++) {
        int di = threadIdx.x + u * 256;
        float o = (vals[u] - mu) * rstd * g[di] + bb[di];
        xc_out[(size_t)bs * DII + di] = o;
        nrm += o * o;
    }
    __syncthreads();
    nrm = warp_sum(nrm);
    if (lane == 0) ssum[wid] = nrm;
    __syncthreads();
    if (threadIdx.x == 0) {
        float tn = 0.f;
#pragma unroll
        for (int w = 0; w < 8; w++) tn += ssum[w];
        xnorm_out[bs] = fminf(sqrtf(tn), 1.0f);
    }
}

// ---------------- K3b: coefficient prep (sums 4 K-split xproj partials) -----
__global__ void coeff_kernel(const float* __restrict__ p,   // 4 parts of [BSS,48]
                             const float* __restrict__ xnorm,
                             const float* __restrict__ dtw,
                             const float* __restrict__ dtb,
                             const float* __restrict__ alog,
                             float* __restrict__ coeff) {
    int row = blockIdx.x * 16 + (threadIdx.x >> 4);
    int i = threadIdx.x & 15;
    const float* pr0 = p + (size_t)row * 48;
    const size_t PS = (size_t)BSS * 48;

    float bm = 0.f, cm = 0.f;
    float dtp[16];
#pragma unroll
    for (int j = 0; j < 16; j++) dtp[j] = 0.f;
#pragma unroll
    for (int z = 0; z < 4; z++) {
        const float* pr = pr0 + z * PS;
        bm += pr[i];
        cm += pr[16 + i];
#pragma unroll
        for (int j = 0; j < 16; j++) dtp[j] += pr[32 + j];
    }
    float acc = dtb[i];
#pragma unroll
    for (int j = 0; j < 16; j++) acc += dtp[j] * dtw[i * 16 + j];
    float dt = tanhf(acc) * 0.01f;
    float ad = 1.0f + dt * (-tanhf(alog[i]));
    size_t base = (size_t)row * 48;
    coeff[base + i]      = ad;
    coeff[base + 16 + i] = bm * xnorm[row];
    coeff[base + 32 + i] = cm;
}

// ---------------- K4: sequential SSM scan + gate ----------------------------
__global__ void scan_kernel(const float* __restrict__ xc,
                            const float* __restrict__ coeff,
                            const float* __restrict__ proj,
                            const float* __restrict__ dparam,
                            float* __restrict__ yg) {
    int blk = blockIdx.x;
    int b   = blk >> 5;
    int di  = ((blk & 31) << 5) + threadIdx.x;

    float h[16];
#pragma unroll
    for (int k = 0; k < 16; k++) h[k] = 0.0f;
    float dp = dparam[di];

    const float*  xrow = xc   + (size_t)b * SS * DII + di;
    const float*  grow = proj + (size_t)b * SS * (2 * DII) + DII + di;
    float*        orow = yg   + (size_t)b * SS * DII + di;
    const float4* cf   = (const float4*)(coeff + (size_t)b * SS * 48);

    float c0[48];
    float x0, g0;
#pragma unroll
    for (int q = 0; q < 12; q++) ((float4*)c0)[q] = __ldg(&cf[q]);
    x0 = __ldg(xrow);
    g0 = __ldg(grow);

    for (int tt = 0; tt < SS; tt++) {
        float c1[48];
        float x1 = 0.f, g1 = 0.f;
        if (tt + 1 < SS) {
            const float4* cf1 = cf + 12;
#pragma unroll
            for (int q = 0; q < 12; q++) ((float4*)c1)[q] = __ldg(&cf1[q]);
            x1 = __ldg(xrow + DII);
            g1 = __ldg(grow + 2 * DII);
        }
        float y = dp * x0;
#pragma unroll
        for (int k = 0; k < 16; k++) {
            float hn = h[k] * c0[k] + c0[16 + k] * x0;
            hn = fminf(fmaxf(hn, -10.0f), 10.0f);
            h[k] = hn;
            y += c0[32 + k] * hn;
        }
        orow[0] = y * silu_f(g0);
        orow += DII; xrow += DII; grow += 2 * DII; cf += 12;
#pragma unroll
        for (int q = 0; q < 48; q++) c0[q] = c1[q];
        x0 = x1; g0 = g1;
    }
}

// ---------------- orchestration ---------------------------------------------
extern "C" void kernel_launch(void* const* d_in, const int* in_sizes, int n_in,
                              void* d_out, int out_size) {
    (void)in_sizes; (void)n_in; (void)out_size;
    const int*   x        = (const int*)  d_in[0];
    const int*   t        = (const int*)  d_in[1];
    const float* emb      = (const float*)d_in[2];
    const float* pos      = (const float*)d_in[3];
    const float* temb     = (const float*)d_in[4];
    const float* in_w     = (const float*)d_in[5];
    const float* conv_w   = (const float*)d_in[6];
    const float* conv_b   = (const float*)d_in[7];
    const float* ln_g     = (const float*)d_in[8];
    const float* ln_b     = (const float*)d_in[9];
    const float* xproj_w  = (const float*)d_in[10];
    const float* dt_w     = (const float*)d_in[11];
    const float* dt_b     = (const float*)d_in[12];
    const float* a_log    = (const float*)d_in[13];
    const float* d_param  = (const float*)d_in[14];
    const float* out_pw   = (const float*)d_in[15];
    const float* out_w    = (const float*)d_in[16];
    const float* out_b    = (const float*)d_in[17];
    float* out = (float*)d_out;

    static float *p_h = nullptr, *p_proj = nullptr, *p_xc = nullptr,
                 *p_coeff = nullptr, *p_yg = nullptr, *p_xn = nullptr, *p_part = nullptr;
    static __half *p_ahi = nullptr, *p_alo = nullptr, *p_bhi = nullptr, *p_blo = nullptr;
    if (!p_h) {
        cudaGetSymbolAddress((void**)&p_h, g_h);
        cudaGetSymbolAddress((void**)&p_proj, g_proj);
        cudaGetSymbolAddress((void**)&p_xc, g_xc);
        cudaGetSymbolAddress((void**)&p_coeff, g_coeff);
        cudaGetSymbolAddress((void**)&p_yg, g_yg);
        cudaGetSymbolAddress((void**)&p_xn, g_xnorm);
        cudaGetSymbolAddress((void**)&p_part, g_part);
        cudaGetSymbolAddress((void**)&p_ahi, g_Ahi);
        cudaGetSymbolAddress((void**)&p_alo, g_Alo);
        cudaGetSymbolAddress((void**)&p_bhi, g_Bhi);
        cudaGetSymbolAddress((void**)&p_blo, g_Blo);
        cudaFuncSetAttribute(gemm_f16<3>, cudaFuncAttributeMaxDynamicSharedMemorySize, 2 * STAGE3);
        cudaFuncSetAttribute(gemm_f16<2>, cudaFuncAttributeMaxDynamicSharedMemorySize, 2 * STAGE2);
    }

    embed_kernel<<<BSS, 128>>>(x, emb, pos, p_h);

    for (int l = 0; l < NL; l++) {
        // proj = h @ in_w[l]   (M=2048, N=2048, K=512)
        splitA_kernel<<<(BSS * DD / 4) / 256, 256>>>(p_h, p_ahi, p_alo);
        splitB_kernel<<<(DD * 2 * DII / 4) / 256, 256>>>(
            in_w + (size_t)l * DD * 2 * DII, p_bhi, p_blo, DD, 2 * DII, 2 * DII);
        gemm_f16<3><<<dim3(BSS / 128, (2 * DII) / 128, 1), 256, 2 * STAGE3>>>(
            p_ahi, p_alo, p_bhi, p_blo, p_proj, BSS, 2 * DII, 2 * DII, DD, DD,
            nullptr, nullptr, 0);

        conv_silu_ln_kernel<<<BSS, 256>>>(
            p_proj, t, temb,
            conv_w + (size_t)l * DII * 4, conv_b + (size_t)l * DII,
            ln_g + (size_t)l * DII, ln_b + (size_t)l * DII, p_xc, p_xn);

        // p = xc @ xproj_w   (M=2048, N=48 pad 128, K=1024), K-split 4
        splitA_kernel<<<(BSS * DII / 4) / 256, 256>>>(p_xc, p_ahi, p_alo);
        splitB_kernel<<<(DII * 128 / 4) / 256, 256>>>(
            xproj_w + (size_t)l * DII * 48, p_bhi, p_blo, DII, 48, 128);
        gemm_f16<3><<<dim3(BSS / 128, 1, 4), 256, 2 * STAGE3>>>(
            p_ahi, p_alo, p_bhi, p_blo, p_part, BSS, 48, 128, DII, DII / 4,
            nullptr, nullptr, 0);

        coeff_kernel<<<BSS / 16, 256>>>(
            p_part, p_xn,
            dt_w + (size_t)l * DSS * DSS, dt_b + (size_t)l * DSS,
            a_log + (size_t)l * DSS, p_coeff);

        scan_kernel<<<BB * (DII / 32), 32>>>(
            p_xc, p_coeff, p_proj, d_param + (size_t)l * DII, p_yg);

        // h += yg @ out_proj_w[l]   (M=2048, N=512, K=1024), K-split 2 + reduce
        splitA_kernel<<<(BSS * DII / 4) / 256, 256>>>(p_yg, p_ahi, p_alo);
        splitB_kernel<<<(DII * DD / 4) / 256, 256>>>(
            out_pw + (size_t)l * DII * DD, p_bhi, p_blo, DII, DD, DD);
        gemm_f16<3><<<dim3(BSS / 128, DD / 128, 2), 256, 2 * STAGE3>>>(
            p_ahi, p_alo, p_bhi, p_blo, p_part, BSS, DD, DD, DII, DII / 2,
            nullptr, nullptr, 0);
        resid_add_kernel<<<(BSS * DD / 4) / 256, 256>>>(p_h, p_part);
    }

    // logits = h @ out_w + out_b  (M=2048, N=50257 pad 50432, K=512), split2
    splitA_kernel<<<(BSS * DD / 4) / 256, 256>>>(p_h, p_ahi, p_alo);
    splitB_kernel<<<(DD * NPADV / 4) / 256, 256>>>(
        out_w, p_bhi, nullptr, DD, VV, NPADV);
    gemm_f16<2><<<dim3(BSS / 128, NPADV / 128, 1), 256, 2 * STAGE2>>>(
        p_ahi, p_alo, p_bhi, nullptr, out, BSS, VV, NPADV, DD, DD,
        out_b, nullptr, 1);
}